// round 3
// baseline (speedup 1.0000x reference)
#include <cuda_runtime.h>
#include <math.h>

// Problem constants
#define BB 2
#define SS 2048
#define EE 2048
#define HH 16
#define DD 128
#define MROWS (BB * SS)   // 4096

// ---------------- scratch (static device globals; no runtime alloc) ----------
__device__ float g_Q[(size_t)BB * HH * SS * DD];   // (B,H,S,D)
__device__ float g_K[(size_t)BB * HH * SS * DD];
__device__ float g_V[(size_t)BB * HH * SS * DD];
__device__ float g_AO[(size_t)BB * SS * EE];       // (B,S,E) attention output

// =============================================================================
// SGEMM: C = A(MxK) @ W(KxN) + bias, fp32.
// Tile 128x128, BK=16, 256 threads, 8x8 per thread.
// headSplit=1: write C[b,h,s,d] layout (B,H,S,D); else row-major MxN.
// =============================================================================
__global__ __launch_bounds__(256) void sgemm_bias(const float* __restrict__ A,
                                                  const float* __restrict__ W,
                                                  const float* __restrict__ bias,
                                                  float* __restrict__ C,
                                                  int headSplit)
{
    const int K = EE, N = EE;
    __shared__ float As[128][16];
    __shared__ float Bs[16][128];

    const int tid = threadIdx.x;
    const int tx = tid & 15;        // n dimension (8 cols each)
    const int ty = tid >> 4;        // m dimension (8 rows each)
    const int m0 = blockIdx.y * 128;
    const int n0 = blockIdx.x * 128;

    float acc[8][8];
#pragma unroll
    for (int i = 0; i < 8; i++)
#pragma unroll
        for (int j = 0; j < 8; j++) acc[i][j] = 0.0f;

    for (int k0 = 0; k0 < K; k0 += 16) {
        // Load A tile 128x16 (coalesced float4)
#pragma unroll
        for (int l = 0; l < 2; l++) {
            int idx = tid + l * 256;          // 0..511 float4 slots
            int r = idx >> 2;                 // row 0..127
            int c = idx & 3;                  // float4 col 0..3
            float4 v = *reinterpret_cast<const float4*>(
                A + (size_t)(m0 + r) * K + k0 + c * 4);
            *reinterpret_cast<float4*>(&As[r][c * 4]) = v;
        }
        // Load B tile 16x128 (coalesced float4)
#pragma unroll
        for (int l = 0; l < 2; l++) {
            int idx = tid + l * 256;
            int r = idx >> 5;                 // row 0..15
            int c = idx & 31;                 // float4 col 0..31
            *reinterpret_cast<float4*>(&Bs[r][c * 4]) =
                *reinterpret_cast<const float4*>(
                    W + (size_t)(k0 + r) * N + n0 + c * 4);
        }
        __syncthreads();

#pragma unroll
        for (int k = 0; k < 16; k++) {
            float a[8], b[8];
#pragma unroll
            for (int i = 0; i < 8; i++) a[i] = As[ty * 8 + i][k];  // broadcast
            *reinterpret_cast<float4*>(b) =
                *reinterpret_cast<float4*>(&Bs[k][tx * 8]);
            *reinterpret_cast<float4*>(b + 4) =
                *reinterpret_cast<float4*>(&Bs[k][tx * 8 + 4]);
#pragma unroll
            for (int i = 0; i < 8; i++)
#pragma unroll
                for (int j = 0; j < 8; j++)
                    acc[i][j] = fmaf(a[i], b[j], acc[i][j]);
        }
        __syncthreads();
    }

    // Epilogue: bias + store
#pragma unroll
    for (int i = 0; i < 8; i++) {
        int m = m0 + ty * 8 + i;
        int bb = m >> 11;           // m / 2048
        int ss = m & 2047;
#pragma unroll
        for (int j = 0; j < 8; j++) {
            int n = n0 + tx * 8 + j;
            float v = acc[i][j] + bias[n];
            if (headSplit) {
                int h = n >> 7;     // n / 128
                int d = n & 127;
                C[(((size_t)bb * HH + h) * SS + ss) * DD + d] = v;
            } else {
                C[(size_t)m * N + n] = v;
            }
        }
    }
}

// =============================================================================
// Flash attention, fp32. One block = 64 query rows of one (b,h).
// 256 threads: tx=tid&15 (keys in QK / d-cols in PV), ty=tid>>4 (queries, 4 each)
// =============================================================================
#define FBQ 64
#define FBK 64
#define PS_STRIDE 68   // padded row stride for Ps (16B-aligned, conflict-free)

__global__ __launch_bounds__(256) void flash_attn(const float* __restrict__ Qg,
                                                  const float* __restrict__ Kg,
                                                  const float* __restrict__ Vg,
                                                  float* __restrict__ Og)
{
    extern __shared__ float sm[];
    float (*Qts)[FBQ]      = reinterpret_cast<float (*)[FBQ]>(sm);           // [128][64]
    float (*Kts)[FBK]      = reinterpret_cast<float (*)[FBK]>(sm + 8192);    // [128][64]
    float (*Vs)[DD]        = reinterpret_cast<float (*)[DD]>(sm + 16384);    // [64][128]
    float (*Ps)[PS_STRIDE] = reinterpret_cast<float (*)[PS_STRIDE]>(sm + 24576); // [64][68]

    const int tid = threadIdx.x;
    const int tx = tid & 15;
    const int ty = tid >> 4;
    const int bh = blockIdx.y;            // 0..31
    const int q0 = blockIdx.x * FBQ;
    const size_t base = (size_t)bh * SS * DD;
    const float scale = 0.08838834764831845f;  // 1/sqrt(128)

    // Load Q tile transposed: lanes walk rows (conflict-free smem store)
#pragma unroll
    for (int l = 0; l < 8; l++) {
        int idx = tid + l * 256;
        int r = idx & 63;          // row within tile
        int c = idx >> 6;          // float4 col 0..31
        float4 v = *reinterpret_cast<const float4*>(
            Qg + base + (size_t)(q0 + r) * DD + c * 4);
        Qts[c * 4 + 0][r] = v.x;
        Qts[c * 4 + 1][r] = v.y;
        Qts[c * 4 + 2][r] = v.z;
        Qts[c * 4 + 3][r] = v.w;
    }

    float m_i[4], l_i[4], o[4][8];
#pragma unroll
    for (int i = 0; i < 4; i++) {
        m_i[i] = -3.402823466e38f;
        l_i[i] = 0.0f;
#pragma unroll
        for (int j = 0; j < 8; j++) o[i][j] = 0.0f;
    }

    for (int kb = 0; kb < SS; kb += FBK) {
        __syncthreads();   // prior-iter PV reads done (and Q stores on iter 0)

        // Load K tile transposed
#pragma unroll
        for (int l = 0; l < 8; l++) {
            int idx = tid + l * 256;
            int r = idx & 63;
            int c = idx >> 6;
            float4 v = *reinterpret_cast<const float4*>(
                Kg + base + (size_t)(kb + r) * DD + c * 4);
            Kts[c * 4 + 0][r] = v.x;
            Kts[c * 4 + 1][r] = v.y;
            Kts[c * 4 + 2][r] = v.z;
            Kts[c * 4 + 3][r] = v.w;
        }
        // Load V tile row-major (coalesced)
#pragma unroll
        for (int l = 0; l < 8; l++) {
            int idx = tid + l * 256;
            int r = idx >> 5;
            int c = idx & 31;
            *reinterpret_cast<float4*>(&Vs[r][c * 4]) =
                *reinterpret_cast<const float4*>(
                    Vg + base + (size_t)(kb + r) * DD + c * 4);
        }
        __syncthreads();

        // S tile: 4x4 per thread over D=128
        float s[4][4];
#pragma unroll
        for (int i = 0; i < 4; i++)
#pragma unroll
            for (int j = 0; j < 4; j++) s[i][j] = 0.0f;

#pragma unroll 8
        for (int d = 0; d < DD; d++) {
            float4 a = *reinterpret_cast<float4*>(&Qts[d][ty * 4]);
            float4 b = *reinterpret_cast<float4*>(&Kts[d][tx * 4]);
            float av[4] = {a.x, a.y, a.z, a.w};
            float bv[4] = {b.x, b.y, b.z, b.w};
#pragma unroll
            for (int i = 0; i < 4; i++)
#pragma unroll
                for (int j = 0; j < 4; j++)
                    s[i][j] = fmaf(av[i], bv[j], s[i][j]);
        }

        // Online softmax update per query row
#pragma unroll
        for (int i = 0; i < 4; i++) {
            float mx = -3.402823466e38f;
#pragma unroll
            for (int j = 0; j < 4; j++) {
                s[i][j] *= scale;
                mx = fmaxf(mx, s[i][j]);
            }
            // max across the 16 tx lanes (xor <= 8 stays in half-warp)
#pragma unroll
            for (int off = 8; off >= 1; off >>= 1)
                mx = fmaxf(mx, __shfl_xor_sync(0xffffffffu, mx, off));

            float mnew = fmaxf(m_i[i], mx);
            float corr = __expf(m_i[i] - mnew);

            float4 pv;
            float p0 = __expf(s[i][0] - mnew);
            float p1 = __expf(s[i][1] - mnew);
            float p2 = __expf(s[i][2] - mnew);
            float p3 = __expf(s[i][3] - mnew);
            pv.x = p0; pv.y = p1; pv.z = p2; pv.w = p3;
            *reinterpret_cast<float4*>(&Ps[ty * 4 + i][tx * 4]) = pv;

            float psum = p0 + p1 + p2 + p3;
#pragma unroll
            for (int off = 8; off >= 1; off >>= 1)
                psum += __shfl_xor_sync(0xffffffffu, psum, off);

            l_i[i] = l_i[i] * corr + psum;
            m_i[i] = mnew;
#pragma unroll
            for (int j = 0; j < 8; j++) o[i][j] *= corr;
        }
        __syncthreads();   // Ps visible to all

        // O += P @ V   (per thread: 4 q-rows x 8 d-cols)
#pragma unroll 4
        for (int kk = 0; kk < FBK; kk++) {
            float4 v0 = *reinterpret_cast<float4*>(&Vs[kk][tx * 8]);
            float4 v1 = *reinterpret_cast<float4*>(&Vs[kk][tx * 8 + 4]);
#pragma unroll
            for (int i = 0; i < 4; i++) {
                float p = Ps[ty * 4 + i][kk];     // broadcast (2 addrs/warp)
                o[i][0] = fmaf(p, v0.x, o[i][0]);
                o[i][1] = fmaf(p, v0.y, o[i][1]);
                o[i][2] = fmaf(p, v0.z, o[i][2]);
                o[i][3] = fmaf(p, v0.w, o[i][3]);
                o[i][4] = fmaf(p, v1.x, o[i][4]);
                o[i][5] = fmaf(p, v1.y, o[i][5]);
                o[i][6] = fmaf(p, v1.z, o[i][6]);
                o[i][7] = fmaf(p, v1.w, o[i][7]);
            }
        }
    }

    // Normalize and write to (B,S,E)
    const int b = bh >> 4;
    const int h = bh & 15;
#pragma unroll
    for (int i = 0; i < 4; i++) {
        float inv = 1.0f / l_i[i];
        int q = q0 + ty * 4 + i;
        size_t off = ((size_t)b * SS + q) * EE + h * DD + tx * 8;
        float4 r0, r1;
        r0.x = o[i][0] * inv; r0.y = o[i][1] * inv;
        r0.z = o[i][2] * inv; r0.w = o[i][3] * inv;
        r1.x = o[i][4] * inv; r1.y = o[i][5] * inv;
        r1.z = o[i][6] * inv; r1.w = o[i][7] * inv;
        *reinterpret_cast<float4*>(Og + off) = r0;
        *reinterpret_cast<float4*>(Og + off + 4) = r1;
    }
}

// =============================================================================
// Launch
// =============================================================================
extern "C" void kernel_launch(void* const* d_in, const int* in_sizes, int n_in,
                              void* d_out, int out_size)
{
    const float* query  = (const float*)d_in[0];
    const float* key_in = (const float*)d_in[1];
    const float* value  = (const float*)d_in[2];
    const float* Wq = (const float*)d_in[3];
    const float* bq = (const float*)d_in[4];
    const float* Wk = (const float*)d_in[5];
    const float* bk = (const float*)d_in[6];
    const float* Wv = (const float*)d_in[7];
    const float* bv = (const float*)d_in[8];
    const float* Wo = (const float*)d_in[9];
    const float* bo = (const float*)d_in[10];
    float* out = (float*)d_out;

    float *qBuf, *kBuf, *vBuf, *aoBuf;
    cudaGetSymbolAddress((void**)&qBuf,  g_Q);
    cudaGetSymbolAddress((void**)&kBuf,  g_K);
    cudaGetSymbolAddress((void**)&vBuf,  g_V);
    cudaGetSymbolAddress((void**)&aoBuf, g_AO);

    dim3 gGrid(EE / 128, MROWS / 128);  // (16, 32)
    sgemm_bias<<<gGrid, 256>>>(query,  Wq, bq, qBuf, 1);
    sgemm_bias<<<gGrid, 256>>>(key_in, Wk, bk, kBuf, 1);
    sgemm_bias<<<gGrid, 256>>>(value,  Wv, bv, vBuf, 1);

    const int FLASH_SMEM = (8192 + 8192 + 8192 + 64 * PS_STRIDE) * 4;  // 115712 B
    cudaFuncSetAttribute(flash_attn,
                         cudaFuncAttributeMaxDynamicSharedMemorySize, FLASH_SMEM);
    dim3 fGrid(SS / FBQ, BB * HH);      // (32, 32)
    flash_attn<<<fGrid, 256, FLASH_SMEM>>>(qBuf, kBuf, vBuf, aoBuf);

    sgemm_bias<<<gGrid, 256>>>(aoBuf, Wo, bo, out, 0);
}

// round 7
// speedup vs baseline: 1.6390x; 1.6390x over previous
#include <cuda_runtime.h>
#include <cuda_bf16.h>
#include <math.h>

// Problem constants
#define BB 2
#define SS 2048
#define EE 2048
#define HH 16
#define DD 128
#define MROWS (BB * SS)   // 4096

// ---------------- scratch (static device globals; no runtime alloc) ----------
__device__ float g_Q[(size_t)BB * HH * SS * DD];   // (B,H,S,D)
__device__ float g_K[(size_t)BB * HH * SS * DD];
__device__ float g_V[(size_t)BB * HH * SS * DD];
__device__ float g_AO[(size_t)BB * SS * EE];       // (B,S,E) attention output

// ---------------- mma / ldmatrix helpers -------------------------------------
__device__ __forceinline__ unsigned smem_u32(const void* p) {
    return (unsigned)__cvta_generic_to_shared(p);
}

__device__ __forceinline__ void ldsm4(unsigned* r, unsigned addr) {
    asm volatile("ldmatrix.sync.aligned.m8n8.x4.shared.b16 {%0,%1,%2,%3}, [%4];\n"
                 : "=r"(r[0]), "=r"(r[1]), "=r"(r[2]), "=r"(r[3]) : "r"(addr));
}
__device__ __forceinline__ void ldsm4t(unsigned* r, unsigned addr) {
    asm volatile("ldmatrix.sync.aligned.m8n8.x4.trans.shared.b16 {%0,%1,%2,%3}, [%4];\n"
                 : "=r"(r[0]), "=r"(r[1]), "=r"(r[2]), "=r"(r[3]) : "r"(addr));
}
__device__ __forceinline__ void mma16816(float* c, const unsigned* a,
                                         unsigned b0, unsigned b1) {
    asm volatile(
        "mma.sync.aligned.m16n8k16.row.col.f32.bf16.bf16.f32 "
        "{%0,%1,%2,%3}, {%4,%5,%6,%7}, {%8,%9}, {%0,%1,%2,%3};\n"
        : "+f"(c[0]), "+f"(c[1]), "+f"(c[2]), "+f"(c[3])
        : "r"(a[0]), "r"(a[1]), "r"(a[2]), "r"(a[3]), "r"(b0), "r"(b1));
}

// =============================================================================
// Split-bf16 tensor-core GEMM: C = A(MxK) @ W(KxN) + bias, fp32 accuracy.
// A*B ~= Ah*Bh + Ah*Bl + Al*Bh  (3-term bf16 expansion, err ~2^-16)
// Block tile 128x128, BK=32, 256 threads = 8 warps (4x2), warp tile 32x64.
// headSplit=1: write (B,H,S,D); else row-major MxN.
// =============================================================================
#define ASTR 40    // A smem row stride in bf16 (80B: ldmatrix conflict-free)
#define BSTR 136   // B smem row stride in bf16 (272B: ldmatrix conflict-free)

__global__ __launch_bounds__(256) void gemm_bf16split(const float* __restrict__ A,
                                                      const float* __restrict__ W,
                                                      const float* __restrict__ bias,
                                                      float* __restrict__ C,
                                                      int headSplit)
{
    const int K = EE, N = EE;
    __shared__ __align__(16) __nv_bfloat16 Ah[128][ASTR];
    __shared__ __align__(16) __nv_bfloat16 Al[128][ASTR];
    __shared__ __align__(16) __nv_bfloat16 Bh[32][BSTR];
    __shared__ __align__(16) __nv_bfloat16 Bl[32][BSTR];

    const int tid  = threadIdx.x;
    const int lane = tid & 31;
    const int warp = tid >> 5;
    const int wm = (warp & 3) * 32;   // warp m offset in block tile
    const int wn = (warp >> 2) * 64;  // warp n offset
    const int m0 = blockIdx.y * 128;
    const int n0 = blockIdx.x * 128;

    // ldmatrix lane-address components
    const int lr  = lane & 15;         // row within 16
    const int lk8 = (lane >> 4) * 8;   // 0 or 8 (second pair of 8x8 tiles)

    float acc[2][8][4];
#pragma unroll
    for (int mt = 0; mt < 2; mt++)
#pragma unroll
        for (int nt = 0; nt < 8; nt++)
#pragma unroll
            for (int j = 0; j < 4; j++) acc[mt][nt][j] = 0.0f;

    float4 pa[4], pb[4];

    // ---- tile loaders (registers <- global) ----
#define LOAD_TILES(k0)                                                          \
    {                                                                           \
        _Pragma("unroll")                                                       \
        for (int l = 0; l < 4; l++) {                                           \
            int idx = l * 256 + tid;                                            \
            int r = idx >> 3, c = idx & 7;                                      \
            pa[l] = *reinterpret_cast<const float4*>(                           \
                A + (size_t)(m0 + r) * K + (k0) + c * 4);                       \
        }                                                                       \
        _Pragma("unroll")                                                       \
        for (int l = 0; l < 4; l++) {                                           \
            int idx = l * 256 + tid;                                            \
            int r = idx >> 5, c = idx & 31;                                     \
            pb[l] = *reinterpret_cast<const float4*>(                           \
                W + (size_t)((k0) + r) * N + n0 + c * 4);                       \
        }                                                                       \
    }

    // ---- convert + store (registers -> smem hi/lo) ----
#define STORE_TILES()                                                           \
    {                                                                           \
        _Pragma("unroll")                                                       \
        for (int l = 0; l < 4; l++) {                                           \
            int idx = l * 256 + tid;                                            \
            int r = idx >> 3, c = (idx & 7) * 4;                                \
            float4 v = pa[l];                                                   \
            __nv_bfloat162 h01 = __floats2bfloat162_rn(v.x, v.y);               \
            __nv_bfloat162 h23 = __floats2bfloat162_rn(v.z, v.w);               \
            __nv_bfloat162 l01 = __floats2bfloat162_rn(                         \
                v.x - __low2float(h01), v.y - __high2float(h01));               \
            __nv_bfloat162 l23 = __floats2bfloat162_rn(                         \
                v.z - __low2float(h23), v.w - __high2float(h23));               \
            *reinterpret_cast<__nv_bfloat162*>(&Ah[r][c])     = h01;            \
            *reinterpret_cast<__nv_bfloat162*>(&Ah[r][c + 2]) = h23;            \
            *reinterpret_cast<__nv_bfloat162*>(&Al[r][c])     = l01;            \
            *reinterpret_cast<__nv_bfloat162*>(&Al[r][c + 2]) = l23;            \
        }                                                                       \
        _Pragma("unroll")                                                       \
        for (int l = 0; l < 4; l++) {                                           \
            int idx = l * 256 + tid;                                            \
            int r = idx >> 5, c = (idx & 31) * 4;                               \
            float4 v = pb[l];                                                   \
            __nv_bfloat162 h01 = __floats2bfloat162_rn(v.x, v.y);               \
            __nv_bfloat162 h23 = __floats2bfloat162_rn(v.z, v.w);               \
            __nv_bfloat162 l01 = __floats2bfloat162_rn(                         \
                v.x - __low2float(h01), v.y - __high2float(h01));               \
            __nv_bfloat162 l23 = __floats2bfloat162_rn(                         \
                v.z - __low2float(h23), v.w - __high2float(h23));               \
            *reinterpret_cast<__nv_bfloat162*>(&Bh[r][c])     = h01;            \
            *reinterpret_cast<__nv_bfloat162*>(&Bh[r][c + 2]) = h23;            \
            *reinterpret_cast<__nv_bfloat162*>(&Bl[r][c])     = l01;            \
            *reinterpret_cast<__nv_bfloat162*>(&Bl[r][c + 2]) = l23;            \
        }                                                                       \
    }

    LOAD_TILES(0);
    STORE_TILES();
    __syncthreads();

    for (int k0 = 0; k0 < K; k0 += 32) {
        const bool more = (k0 + 32) < K;
        if (more) LOAD_TILES(k0 + 32);   // prefetch overlaps with mma below

#pragma unroll
        for (int kk = 0; kk < 32; kk += 16) {
            unsigned ah[2][4], al[2][4];
            ldsm4(ah[0], smem_u32(&Ah[wm + lr][kk + lk8]));
            ldsm4(ah[1], smem_u32(&Ah[wm + 16 + lr][kk + lk8]));
            ldsm4(al[0], smem_u32(&Al[wm + lr][kk + lk8]));
            ldsm4(al[1], smem_u32(&Al[wm + 16 + lr][kk + lk8]));

#pragma unroll
            for (int nb = 0; nb < 4; nb++) {
                unsigned bh[4], bl[4];
                ldsm4t(bh, smem_u32(&Bh[kk + lr][wn + nb * 16 + lk8]));
                ldsm4t(bl, smem_u32(&Bl[kk + lr][wn + nb * 16 + lk8]));
#pragma unroll
                for (int mt = 0; mt < 2; mt++) {
                    mma16816(acc[mt][2 * nb],     ah[mt], bh[0], bh[1]);
                    mma16816(acc[mt][2 * nb + 1], ah[mt], bh[2], bh[3]);
                    mma16816(acc[mt][2 * nb],     ah[mt], bl[0], bl[1]);
                    mma16816(acc[mt][2 * nb + 1], ah[mt], bl[2], bl[3]);
                    mma16816(acc[mt][2 * nb],     al[mt], bh[0], bh[1]);
                    mma16816(acc[mt][2 * nb + 1], al[mt], bh[2], bh[3]);
                }
            }
        }

        if (more) {
            __syncthreads();   // all warps done reading current smem tiles
            STORE_TILES();
            __syncthreads();
        }
    }

    // ---- epilogue: bias + store (float2 per c-pair) ----
#pragma unroll
    for (int mt = 0; mt < 2; mt++) {
#pragma unroll
        for (int nt = 0; nt < 8; nt++) {
            int n = n0 + wn + nt * 8 + 2 * (lane & 3);
            float b0 = bias[n], b1 = bias[n + 1];
#pragma unroll
            for (int half = 0; half < 2; half++) {
                int m = m0 + wm + mt * 16 + (lane >> 2) + half * 8;
                float2 v;
                v.x = acc[mt][nt][2 * half]     + b0;
                v.y = acc[mt][nt][2 * half + 1] + b1;
                if (headSplit) {
                    int bb = m >> 11, ss = m & 2047;
                    int h = n >> 7, d = n & 127;
                    *reinterpret_cast<float2*>(
                        &C[(((size_t)bb * HH + h) * SS + ss) * DD + d]) = v;
                } else {
                    *reinterpret_cast<float2*>(&C[(size_t)m * N + n]) = v;
                }
            }
        }
    }
#undef LOAD_TILES
#undef STORE_TILES
}

// =============================================================================
// Flash attention, fp32 (unchanged from validated R2 version).
// =============================================================================
#define FBQ 64
#define FBK 64
#define PS_STRIDE 68

__global__ __launch_bounds__(256) void flash_attn(const float* __restrict__ Qg,
                                                  const float* __restrict__ Kg,
                                                  const float* __restrict__ Vg,
                                                  float* __restrict__ Og)
{
    extern __shared__ float sm[];
    float (*Qts)[FBQ]      = reinterpret_cast<float (*)[FBQ]>(sm);           // [128][64]
    float (*Kts)[FBK]      = reinterpret_cast<float (*)[FBK]>(sm + 8192);    // [128][64]
    float (*Vs)[DD]        = reinterpret_cast<float (*)[DD]>(sm + 16384);    // [64][128]
    float (*Ps)[PS_STRIDE] = reinterpret_cast<float (*)[PS_STRIDE]>(sm + 24576); // [64][68]

    const int tid = threadIdx.x;
    const int tx = tid & 15;
    const int ty = tid >> 4;
    const int bh = blockIdx.y;
    const int q0 = blockIdx.x * FBQ;
    const size_t base = (size_t)bh * SS * DD;
    const float scale = 0.08838834764831845f;

#pragma unroll
    for (int l = 0; l < 8; l++) {
        int idx = tid + l * 256;
        int r = idx & 63;
        int c = idx >> 6;
        float4 v = *reinterpret_cast<const float4*>(
            Qg + base + (size_t)(q0 + r) * DD + c * 4);
        Qts[c * 4 + 0][r] = v.x;
        Qts[c * 4 + 1][r] = v.y;
        Qts[c * 4 + 2][r] = v.z;
        Qts[c * 4 + 3][r] = v.w;
    }

    float m_i[4], l_i[4], o[4][8];
#pragma unroll
    for (int i = 0; i < 4; i++) {
        m_i[i] = -3.402823466e38f;
        l_i[i] = 0.0f;
#pragma unroll
        for (int j = 0; j < 8; j++) o[i][j] = 0.0f;
    }

    for (int kb = 0; kb < SS; kb += FBK) {
        __syncthreads();

#pragma unroll
        for (int l = 0; l < 8; l++) {
            int idx = tid + l * 256;
            int r = idx & 63;
            int c = idx >> 6;
            float4 v = *reinterpret_cast<const float4*>(
                Kg + base + (size_t)(kb + r) * DD + c * 4);
            Kts[c * 4 + 0][r] = v.x;
            Kts[c * 4 + 1][r] = v.y;
            Kts[c * 4 + 2][r] = v.z;
            Kts[c * 4 + 3][r] = v.w;
        }
#pragma unroll
        for (int l = 0; l < 8; l++) {
            int idx = tid + l * 256;
            int r = idx >> 5;
            int c = idx & 31;
            *reinterpret_cast<float4*>(&Vs[r][c * 4]) =
                *reinterpret_cast<const float4*>(
                    Vg + base + (size_t)(kb + r) * DD + c * 4);
        }
        __syncthreads();

        float s[4][4];
#pragma unroll
        for (int i = 0; i < 4; i++)
#pragma unroll
            for (int j = 0; j < 4; j++) s[i][j] = 0.0f;

#pragma unroll 8
        for (int d = 0; d < DD; d++) {
            float4 a = *reinterpret_cast<float4*>(&Qts[d][ty * 4]);
            float4 b = *reinterpret_cast<float4*>(&Kts[d][tx * 4]);
            float av[4] = {a.x, a.y, a.z, a.w};
            float bv[4] = {b.x, b.y, b.z, b.w};
#pragma unroll
            for (int i = 0; i < 4; i++)
#pragma unroll
                for (int j = 0; j < 4; j++)
                    s[i][j] = fmaf(av[i], bv[j], s[i][j]);
        }

#pragma unroll
        for (int i = 0; i < 4; i++) {
            float mx = -3.402823466e38f;
#pragma unroll
            for (int j = 0; j < 4; j++) {
                s[i][j] *= scale;
                mx = fmaxf(mx, s[i][j]);
            }
#pragma unroll
            for (int off = 8; off >= 1; off >>= 1)
                mx = fmaxf(mx, __shfl_xor_sync(0xffffffffu, mx, off));

            float mnew = fmaxf(m_i[i], mx);
            float corr = __expf(m_i[i] - mnew);

            float4 pv;
            float p0 = __expf(s[i][0] - mnew);
            float p1 = __expf(s[i][1] - mnew);
            float p2 = __expf(s[i][2] - mnew);
            float p3 = __expf(s[i][3] - mnew);
            pv.x = p0; pv.y = p1; pv.z = p2; pv.w = p3;
            *reinterpret_cast<float4*>(&Ps[ty * 4 + i][tx * 4]) = pv;

            float psum = p0 + p1 + p2 + p3;
#pragma unroll
            for (int off = 8; off >= 1; off >>= 1)
                psum += __shfl_xor_sync(0xffffffffu, psum, off);

            l_i[i] = l_i[i] * corr + psum;
            m_i[i] = mnew;
#pragma unroll
            for (int j = 0; j < 8; j++) o[i][j] *= corr;
        }
        __syncthreads();

#pragma unroll 4
        for (int kk = 0; kk < FBK; kk++) {
            float4 v0 = *reinterpret_cast<float4*>(&Vs[kk][tx * 8]);
            float4 v1 = *reinterpret_cast<float4*>(&Vs[kk][tx * 8 + 4]);
#pragma unroll
            for (int i = 0; i < 4; i++) {
                float p = Ps[ty * 4 + i][kk];
                o[i][0] = fmaf(p, v0.x, o[i][0]);
                o[i][1] = fmaf(p, v0.y, o[i][1]);
                o[i][2] = fmaf(p, v0.z, o[i][2]);
                o[i][3] = fmaf(p, v0.w, o[i][3]);
                o[i][4] = fmaf(p, v1.x, o[i][4]);
                o[i][5] = fmaf(p, v1.y, o[i][5]);
                o[i][6] = fmaf(p, v1.z, o[i][6]);
                o[i][7] = fmaf(p, v1.w, o[i][7]);
            }
        }
    }

    const int b = bh >> 4;
    const int h = bh & 15;
#pragma unroll
    for (int i = 0; i < 4; i++) {
        float inv = 1.0f / l_i[i];
        int q = q0 + ty * 4 + i;
        size_t off = ((size_t)b * SS + q) * EE + h * DD + tx * 8;
        float4 r0, r1;
        r0.x = o[i][0] * inv; r0.y = o[i][1] * inv;
        r0.z = o[i][2] * inv; r0.w = o[i][3] * inv;
        r1.x = o[i][4] * inv; r1.y = o[i][5] * inv;
        r1.z = o[i][6] * inv; r1.w = o[i][7] * inv;
        *reinterpret_cast<float4*>(Og + off) = r0;
        *reinterpret_cast<float4*>(Og + off + 4) = r1;
    }
}

// =============================================================================
// Launch
// =============================================================================
extern "C" void kernel_launch(void* const* d_in, const int* in_sizes, int n_in,
                              void* d_out, int out_size)
{
    const float* query  = (const float*)d_in[0];
    const float* key_in = (const float*)d_in[1];
    const float* value  = (const float*)d_in[2];
    const float* Wq = (const float*)d_in[3];
    const float* bq = (const float*)d_in[4];
    const float* Wk = (const float*)d_in[5];
    const float* bk = (const float*)d_in[6];
    const float* Wv = (const float*)d_in[7];
    const float* bv = (const float*)d_in[8];
    const float* Wo = (const float*)d_in[9];
    const float* bo = (const float*)d_in[10];
    float* out = (float*)d_out;

    float *qBuf, *kBuf, *vBuf, *aoBuf;
    cudaGetSymbolAddress((void**)&qBuf,  g_Q);
    cudaGetSymbolAddress((void**)&kBuf,  g_K);
    cudaGetSymbolAddress((void**)&vBuf,  g_V);
    cudaGetSymbolAddress((void**)&aoBuf, g_AO);

    dim3 gGrid(EE / 128, MROWS / 128);  // (16, 32)
    gemm_bf16split<<<gGrid, 256>>>(query,  Wq, bq, qBuf, 1);
    gemm_bf16split<<<gGrid, 256>>>(key_in, Wk, bk, kBuf, 1);
    gemm_bf16split<<<gGrid, 256>>>(value,  Wv, bv, vBuf, 1);

    const int FLASH_SMEM = (8192 + 8192 + 8192 + 64 * PS_STRIDE) * 4;  // 115712 B
    cudaFuncSetAttribute(flash_attn,
                         cudaFuncAttributeMaxDynamicSharedMemorySize, FLASH_SMEM);
    dim3 fGrid(SS / FBQ, BB * HH);      // (32, 32)
    flash_attn<<<fGrid, 256, FLASH_SMEM>>>(qBuf, kBuf, vBuf, aoBuf);

    gemm_bf16split<<<gGrid, 256>>>(aoBuf, Wo, bo, out, 0);
}

// round 9
// speedup vs baseline: 2.6460x; 1.6144x over previous
#include <cuda_runtime.h>
#include <cuda_bf16.h>
#include <math.h>

// Problem constants
#define BB 2
#define SS 2048
#define EE 2048
#define HH 16
#define DD 128
#define MROWS (BB * SS)   // 4096

// ---------------- scratch (static device globals; no runtime alloc) ----------
__device__ float g_Q[(size_t)BB * HH * SS * DD];   // (B,H,S,D)
__device__ float g_K[(size_t)BB * HH * SS * DD];
__device__ float g_V[(size_t)BB * HH * SS * DD];
__device__ float g_AO[(size_t)BB * SS * EE];       // (B,S,E) attention output

// ---------------- mma / ldmatrix helpers -------------------------------------
__device__ __forceinline__ unsigned smem_u32(const void* p) {
    return (unsigned)__cvta_generic_to_shared(p);
}
__device__ __forceinline__ void ldsm4(unsigned* r, unsigned addr) {
    asm volatile("ldmatrix.sync.aligned.m8n8.x4.shared.b16 {%0,%1,%2,%3}, [%4];\n"
                 : "=r"(r[0]), "=r"(r[1]), "=r"(r[2]), "=r"(r[3]) : "r"(addr));
}
__device__ __forceinline__ void ldsm4t(unsigned* r, unsigned addr) {
    asm volatile("ldmatrix.sync.aligned.m8n8.x4.trans.shared.b16 {%0,%1,%2,%3}, [%4];\n"
                 : "=r"(r[0]), "=r"(r[1]), "=r"(r[2]), "=r"(r[3]) : "r"(addr));
}
__device__ __forceinline__ void mma16816(float* c, const unsigned* a,
                                         unsigned b0, unsigned b1) {
    asm volatile(
        "mma.sync.aligned.m16n8k16.row.col.f32.bf16.bf16.f32 "
        "{%0,%1,%2,%3}, {%4,%5,%6,%7}, {%8,%9}, {%0,%1,%2,%3};\n"
        : "+f"(c[0]), "+f"(c[1]), "+f"(c[2]), "+f"(c[3])
        : "r"(a[0]), "r"(a[1]), "r"(a[2]), "r"(a[3]), "r"(b0), "r"(b1));
}
__device__ __forceinline__ float ex2f(float x) {
    float y;
    asm("ex2.approx.ftz.f32 %0, %1;" : "=f"(y) : "f"(x));
    return y;
}
// split (x,y) into packed bf16 hi and lo residual pairs
__device__ __forceinline__ void split2(float x, float y, unsigned& hi, unsigned& lo) {
    __nv_bfloat162 h = __floats2bfloat162_rn(x, y);
    __nv_bfloat162 l = __floats2bfloat162_rn(x - __low2float(h), y - __high2float(h));
    hi = *reinterpret_cast<unsigned*>(&h);
    lo = *reinterpret_cast<unsigned*>(&l);
}

// =============================================================================
// Split-bf16 tensor-core GEMM: C = A(MxK) @ W(KxN) + bias, fp32 accuracy.
// (unchanged from R7 — validated)
// =============================================================================
#define ASTR 40
#define BSTR 136

__global__ __launch_bounds__(256) void gemm_bf16split(const float* __restrict__ A,
                                                      const float* __restrict__ W,
                                                      const float* __restrict__ bias,
                                                      float* __restrict__ C,
                                                      int headSplit)
{
    const int K = EE, N = EE;
    __shared__ __align__(16) __nv_bfloat16 Ah[128][ASTR];
    __shared__ __align__(16) __nv_bfloat16 Al[128][ASTR];
    __shared__ __align__(16) __nv_bfloat16 Bh[32][BSTR];
    __shared__ __align__(16) __nv_bfloat16 Bl[32][BSTR];

    const int tid  = threadIdx.x;
    const int lane = tid & 31;
    const int warp = tid >> 5;
    const int wm = (warp & 3) * 32;
    const int wn = (warp >> 2) * 64;
    const int m0 = blockIdx.y * 128;
    const int n0 = blockIdx.x * 128;
    const int lr  = lane & 15;
    const int lk8 = (lane >> 4) * 8;

    float acc[2][8][4];
#pragma unroll
    for (int mt = 0; mt < 2; mt++)
#pragma unroll
        for (int nt = 0; nt < 8; nt++)
#pragma unroll
            for (int j = 0; j < 4; j++) acc[mt][nt][j] = 0.0f;

    float4 pa[4], pb[4];

#define LOAD_TILES(k0)                                                          \
    {                                                                           \
        _Pragma("unroll")                                                       \
        for (int l = 0; l < 4; l++) {                                           \
            int idx = l * 256 + tid;                                            \
            int r = idx >> 3, c = idx & 7;                                      \
            pa[l] = *reinterpret_cast<const float4*>(                           \
                A + (size_t)(m0 + r) * K + (k0) + c * 4);                       \
        }                                                                       \
        _Pragma("unroll")                                                       \
        for (int l = 0; l < 4; l++) {                                           \
            int idx = l * 256 + tid;                                            \
            int r = idx >> 5, c = idx & 31;                                     \
            pb[l] = *reinterpret_cast<const float4*>(                           \
                W + (size_t)((k0) + r) * N + n0 + c * 4);                       \
        }                                                                       \
    }

#define STORE_TILES()                                                           \
    {                                                                           \
        _Pragma("unroll")                                                       \
        for (int l = 0; l < 4; l++) {                                           \
            int idx = l * 256 + tid;                                            \
            int r = idx >> 3, c = (idx & 7) * 4;                                \
            float4 v = pa[l];                                                   \
            unsigned h01, l01, h23, l23;                                        \
            split2(v.x, v.y, h01, l01);                                         \
            split2(v.z, v.w, h23, l23);                                         \
            *reinterpret_cast<unsigned*>(&Ah[r][c])     = h01;                  \
            *reinterpret_cast<unsigned*>(&Ah[r][c + 2]) = h23;                  \
            *reinterpret_cast<unsigned*>(&Al[r][c])     = l01;                  \
            *reinterpret_cast<unsigned*>(&Al[r][c + 2]) = l23;                  \
        }                                                                       \
        _Pragma("unroll")                                                       \
        for (int l = 0; l < 4; l++) {                                           \
            int idx = l * 256 + tid;                                            \
            int r = idx >> 5, c = (idx & 31) * 4;                               \
            float4 v = pb[l];                                                   \
            unsigned h01, l01, h23, l23;                                        \
            split2(v.x, v.y, h01, l01);                                         \
            split2(v.z, v.w, h23, l23);                                         \
            *reinterpret_cast<unsigned*>(&Bh[r][c])     = h01;                  \
            *reinterpret_cast<unsigned*>(&Bh[r][c + 2]) = h23;                  \
            *reinterpret_cast<unsigned*>(&Bl[r][c])     = l01;                  \
            *reinterpret_cast<unsigned*>(&Bl[r][c + 2]) = l23;                  \
        }                                                                       \
    }

    LOAD_TILES(0);
    STORE_TILES();
    __syncthreads();

    for (int k0 = 0; k0 < K; k0 += 32) {
        const bool more = (k0 + 32) < K;
        if (more) LOAD_TILES(k0 + 32);

#pragma unroll
        for (int kk = 0; kk < 32; kk += 16) {
            unsigned ah[2][4], al[2][4];
            ldsm4(ah[0], smem_u32(&Ah[wm + lr][kk + lk8]));
            ldsm4(ah[1], smem_u32(&Ah[wm + 16 + lr][kk + lk8]));
            ldsm4(al[0], smem_u32(&Al[wm + lr][kk + lk8]));
            ldsm4(al[1], smem_u32(&Al[wm + 16 + lr][kk + lk8]));

#pragma unroll
            for (int nb = 0; nb < 4; nb++) {
                unsigned bh[4], bl[4];
                ldsm4t(bh, smem_u32(&Bh[kk + lr][wn + nb * 16 + lk8]));
                ldsm4t(bl, smem_u32(&Bl[kk + lr][wn + nb * 16 + lk8]));
#pragma unroll
                for (int mt = 0; mt < 2; mt++) {
                    mma16816(acc[mt][2 * nb],     ah[mt], bh[0], bh[1]);
                    mma16816(acc[mt][2 * nb + 1], ah[mt], bh[2], bh[3]);
                    mma16816(acc[mt][2 * nb],     ah[mt], bl[0], bl[1]);
                    mma16816(acc[mt][2 * nb + 1], ah[mt], bl[2], bl[3]);
                    mma16816(acc[mt][2 * nb],     al[mt], bh[0], bh[1]);
                    mma16816(acc[mt][2 * nb + 1], al[mt], bh[2], bh[3]);
                }
            }
        }

        if (more) {
            __syncthreads();
            STORE_TILES();
            __syncthreads();
        }
    }

#pragma unroll
    for (int mt = 0; mt < 2; mt++) {
#pragma unroll
        for (int nt = 0; nt < 8; nt++) {
            int n = n0 + wn + nt * 8 + 2 * (lane & 3);
            float b0 = bias[n], b1 = bias[n + 1];
#pragma unroll
            for (int half = 0; half < 2; half++) {
                int m = m0 + wm + mt * 16 + (lane >> 2) + half * 8;
                float2 v;
                v.x = acc[mt][nt][2 * half]     + b0;
                v.y = acc[mt][nt][2 * half + 1] + b1;
                if (headSplit) {
                    int bb = m >> 11, ss = m & 2047;
                    int h = n >> 7, d = n & 127;
                    *reinterpret_cast<float2*>(
                        &C[(((size_t)bb * HH + h) * SS + ss) * DD + d]) = v;
                } else {
                    *reinterpret_cast<float2*>(&C[(size_t)m * N + n]) = v;
                }
            }
        }
    }
#undef LOAD_TILES
#undef STORE_TILES
}

// =============================================================================
// Tensor-core flash attention (split-bf16, fp32-accurate).
// BQ=128 rows per CTA, BK=64 per iteration. 8 warps; warp w owns rows
// [16w,16w+16) -> softmax stats fully warp-local.
//   S = Q K^T : A=Q (row-major smem, ldsm4), B=K^T stored [d][kv] (ldsm4t)
//   O += P V  : A=P straight from mma accum registers, B=V [kv][d] (ldsm4t)
// 3-term split on both products: err ~2^-16.
// =============================================================================
#define FQ  128
#define FK  64
#define QSTR 136   // Q smem row stride (128 + 8 pad)
#define KSTR 72    // K^T smem row stride (64 + 8 pad)
#define VSTR 136   // V smem row stride

// smem offsets in bf16 elements
#define OFF_QH 0
#define OFF_QL 17408          // 128*136
#define OFF_KH 34816
#define OFF_KL 44032          // +128*72
#define OFF_VH 53248          // +128*72
#define OFF_VL 61952          // +64*136
#define FLASH_SMEM_BF16 70656 // total

__global__ __launch_bounds__(256) void flash_mma(const float* __restrict__ Qg,
                                                 const float* __restrict__ Kg,
                                                 const float* __restrict__ Vg,
                                                 float* __restrict__ Og)
{
    extern __shared__ __align__(16) __nv_bfloat16 smb[];
    __nv_bfloat16 (*Qh)[QSTR]  = reinterpret_cast<__nv_bfloat16 (*)[QSTR]>(smb + OFF_QH);
    __nv_bfloat16 (*Ql)[QSTR]  = reinterpret_cast<__nv_bfloat16 (*)[QSTR]>(smb + OFF_QL);
    __nv_bfloat16 (*Kth)[KSTR] = reinterpret_cast<__nv_bfloat16 (*)[KSTR]>(smb + OFF_KH);
    __nv_bfloat16 (*Ktl)[KSTR] = reinterpret_cast<__nv_bfloat16 (*)[KSTR]>(smb + OFF_KL);
    __nv_bfloat16 (*Vh)[VSTR]  = reinterpret_cast<__nv_bfloat16 (*)[VSTR]>(smb + OFF_VH);
    __nv_bfloat16 (*Vl)[VSTR]  = reinterpret_cast<__nv_bfloat16 (*)[VSTR]>(smb + OFF_VL);

    const int tid  = threadIdx.x;
    const int lane = tid & 31;
    const int warp = tid >> 5;
    const int wq   = warp * 16;         // warp's query-row block
    const int lr   = lane & 15;
    const int lk8  = (lane >> 4) * 8;
    const int bh   = blockIdx.y;        // 0..31  (b*16 + h)
    const int q0   = blockIdx.x * FQ;
    const size_t base = (size_t)bh * SS * DD;

    // log2(e)/sqrt(128): fold scale + exp2 conversion into one multiply
    const float kscale = 0.088388347648318447f * 1.4426950408889634f;

    // ---- load Q tile (128 x 128) -> hi/lo bf16 smem ----
#pragma unroll
    for (int l = 0; l < 16; l++) {
        int idx = l * 256 + tid;
        int r = idx >> 5, c = (idx & 31) * 4;
        float4 v = *reinterpret_cast<const float4*>(
            Qg + base + (size_t)(q0 + r) * DD + c);
        unsigned h01, l01, h23, l23;
        split2(v.x, v.y, h01, l01);
        split2(v.z, v.w, h23, l23);
        *reinterpret_cast<unsigned*>(&Qh[r][c])     = h01;
        *reinterpret_cast<unsigned*>(&Qh[r][c + 2]) = h23;
        *reinterpret_cast<unsigned*>(&Ql[r][c])     = l01;
        *reinterpret_cast<unsigned*>(&Ql[r][c + 2]) = l23;
    }

    float oa[16][4];                    // O accum: 16 d-ntiles x 4
#pragma unroll
    for (int nt = 0; nt < 16; nt++)
#pragma unroll
        for (int j = 0; j < 4; j++) oa[nt][j] = 0.0f;
    float m0 = -1e30f, m1 = -1e30f;     // row stats (rows lane>>2, +8)
    float l0 = 0.0f,  l1 = 0.0f;

    for (int kb = 0; kb < SS; kb += FK) {
        __syncthreads();   // prior-iter smem reads done (iter0: Q stores)

        // ---- load K tile (64 x 128) transposed -> Kt[d][kv] hi/lo ----
#pragma unroll
        for (int l = 0; l < 8; l++) {
            int idx = l * 256 + tid;
            int kv = idx & 63, dq = idx >> 6;       // dq: float4 index 0..31
            float4 v = *reinterpret_cast<const float4*>(
                Kg + base + (size_t)(kb + kv) * DD + dq * 4);
            float vv[4] = {v.x, v.y, v.z, v.w};
#pragma unroll
            for (int j = 0; j < 4; j++) {
                int d = dq * 4 + j;
                __nv_bfloat16 h = __float2bfloat16(vv[j]);
                Kth[d][kv] = h;
                Ktl[d][kv] = __float2bfloat16(vv[j] - __bfloat162float(h));
            }
        }
        // ---- load V tile (64 x 128) row-major hi/lo ----
#pragma unroll
        for (int l = 0; l < 8; l++) {
            int idx = l * 256 + tid;
            int r = idx >> 5, c = (idx & 31) * 4;
            float4 v = *reinterpret_cast<const float4*>(
                Vg + base + (size_t)(kb + r) * DD + c);
            unsigned h01, l01, h23, l23;
            split2(v.x, v.y, h01, l01);
            split2(v.z, v.w, h23, l23);
            *reinterpret_cast<unsigned*>(&Vh[r][c])     = h01;
            *reinterpret_cast<unsigned*>(&Vh[r][c + 2]) = h23;
            *reinterpret_cast<unsigned*>(&Vl[r][c])     = l01;
            *reinterpret_cast<unsigned*>(&Vl[r][c + 2]) = l23;
        }
        __syncthreads();

        // ---- S = Q K^T (warp rows wq..wq+16, all 64 kv cols) ----
        float sa[8][4];
#pragma unroll
        for (int nt = 0; nt < 8; nt++)
#pragma unroll
            for (int j = 0; j < 4; j++) sa[nt][j] = 0.0f;

#pragma unroll
        for (int kk = 0; kk < 8; kk++) {
            unsigned qh[4], qlo[4];
            ldsm4(qh,  smem_u32(&Qh[wq + lr][kk * 16 + lk8]));
            ldsm4(qlo, smem_u32(&Ql[wq + lr][kk * 16 + lk8]));
#pragma unroll
            for (int nb = 0; nb < 4; nb++) {
                unsigned kh[4], kl[4];
                ldsm4t(kh, smem_u32(&Kth[kk * 16 + lr][nb * 16 + lk8]));
                ldsm4t(kl, smem_u32(&Ktl[kk * 16 + lr][nb * 16 + lk8]));
                mma16816(sa[2 * nb],     qh,  kh[0], kh[1]);
                mma16816(sa[2 * nb + 1], qh,  kh[2], kh[3]);
                mma16816(sa[2 * nb],     qh,  kl[0], kl[1]);
                mma16816(sa[2 * nb + 1], qh,  kl[2], kl[3]);
                mma16816(sa[2 * nb],     qlo, kh[0], kh[1]);
                mma16816(sa[2 * nb + 1], qlo, kh[2], kh[3]);
            }
        }

        // ---- online softmax (warp-local; rows r=lane>>2 and r+8) ----
        float mx0 = -1e30f, mx1 = -1e30f;
#pragma unroll
        for (int nt = 0; nt < 8; nt++) {
            sa[nt][0] *= kscale; sa[nt][1] *= kscale;
            sa[nt][2] *= kscale; sa[nt][3] *= kscale;
            mx0 = fmaxf(mx0, fmaxf(sa[nt][0], sa[nt][1]));
            mx1 = fmaxf(mx1, fmaxf(sa[nt][2], sa[nt][3]));
        }
        mx0 = fmaxf(mx0, __shfl_xor_sync(0xffffffffu, mx0, 1));
        mx0 = fmaxf(mx0, __shfl_xor_sync(0xffffffffu, mx0, 2));
        mx1 = fmaxf(mx1, __shfl_xor_sync(0xffffffffu, mx1, 1));
        mx1 = fmaxf(mx1, __shfl_xor_sync(0xffffffffu, mx1, 2));

        float mn0 = fmaxf(m0, mx0);
        float mn1 = fmaxf(m1, mx1);
        float c0 = ex2f(m0 - mn0);
        float c1 = ex2f(m1 - mn1);

        float rs0 = 0.0f, rs1 = 0.0f;
#pragma unroll
        for (int nt = 0; nt < 8; nt++) {
            sa[nt][0] = ex2f(sa[nt][0] - mn0);
            sa[nt][1] = ex2f(sa[nt][1] - mn0);
            sa[nt][2] = ex2f(sa[nt][2] - mn1);
            sa[nt][3] = ex2f(sa[nt][3] - mn1);
            rs0 += sa[nt][0] + sa[nt][1];
            rs1 += sa[nt][2] + sa[nt][3];
        }
        rs0 += __shfl_xor_sync(0xffffffffu, rs0, 1);
        rs0 += __shfl_xor_sync(0xffffffffu, rs0, 2);
        rs1 += __shfl_xor_sync(0xffffffffu, rs1, 1);
        rs1 += __shfl_xor_sync(0xffffffffu, rs1, 2);

        l0 = l0 * c0 + rs0;  m0 = mn0;
        l1 = l1 * c1 + rs1;  m1 = mn1;
#pragma unroll
        for (int nt = 0; nt < 16; nt++) {
            oa[nt][0] *= c0; oa[nt][1] *= c0;
            oa[nt][2] *= c1; oa[nt][3] *= c1;
        }

        // ---- O += P V  (P from accum regs; kv k-chunks of 16) ----
#pragma unroll
        for (int kc = 0; kc < 4; kc++) {
            unsigned pha[4], pla[4];
            split2(sa[2 * kc][0],     sa[2 * kc][1],     pha[0], pla[0]);
            split2(sa[2 * kc][2],     sa[2 * kc][3],     pha[1], pla[1]);
            split2(sa[2 * kc + 1][0], sa[2 * kc + 1][1], pha[2], pla[2]);
            split2(sa[2 * kc + 1][2], sa[2 * kc + 1][3], pha[3], pla[3]);
#pragma unroll
            for (int nb = 0; nb < 8; nb++) {
                unsigned vh[4], vl[4];
                ldsm4t(vh, smem_u32(&Vh[kc * 16 + lr][nb * 16 + lk8]));
                ldsm4t(vl, smem_u32(&Vl[kc * 16 + lr][nb * 16 + lk8]));
                mma16816(oa[2 * nb],     pha, vh[0], vh[1]);
                mma16816(oa[2 * nb + 1], pha, vh[2], vh[3]);
                mma16816(oa[2 * nb],     pha, vl[0], vl[1]);
                mma16816(oa[2 * nb + 1], pha, vl[2], vl[3]);
                mma16816(oa[2 * nb],     pla, vh[0], vh[1]);
                mma16816(oa[2 * nb + 1], pla, vh[2], vh[3]);
            }
        }
    }

    // ---- normalize, write to (B,S,E) ----
    const int b = bh >> 4;
    const int h = bh & 15;
    const float inv0 = 1.0f / l0;
    const float inv1 = 1.0f / l1;
    const int r0 = q0 + wq + (lane >> 2);
    const int d0 = (lane & 3) * 2;
#pragma unroll
    for (int nt = 0; nt < 16; nt++) {
        int d = nt * 8 + d0;
        float2 v0, v1;
        v0.x = oa[nt][0] * inv0; v0.y = oa[nt][1] * inv0;
        v1.x = oa[nt][2] * inv1; v1.y = oa[nt][3] * inv1;
        *reinterpret_cast<float2*>(
            &Og[((size_t)b * SS + r0) * EE + h * DD + d]) = v0;
        *reinterpret_cast<float2*>(
            &Og[((size_t)b * SS + r0 + 8) * EE + h * DD + d]) = v1;
    }
}

// =============================================================================
// Launch
// =============================================================================
extern "C" void kernel_launch(void* const* d_in, const int* in_sizes, int n_in,
                              void* d_out, int out_size)
{
    const float* query  = (const float*)d_in[0];
    const float* key_in = (const float*)d_in[1];
    const float* value  = (const float*)d_in[2];
    const float* Wq = (const float*)d_in[3];
    const float* bq = (const float*)d_in[4];
    const float* Wk = (const float*)d_in[5];
    const float* bk = (const float*)d_in[6];
    const float* Wv = (const float*)d_in[7];
    const float* bv = (const float*)d_in[8];
    const float* Wo = (const float*)d_in[9];
    const float* bo = (const float*)d_in[10];
    float* out = (float*)d_out;

    float *qBuf, *kBuf, *vBuf, *aoBuf;
    cudaGetSymbolAddress((void**)&qBuf,  g_Q);
    cudaGetSymbolAddress((void**)&kBuf,  g_K);
    cudaGetSymbolAddress((void**)&vBuf,  g_V);
    cudaGetSymbolAddress((void**)&aoBuf, g_AO);

    dim3 gGrid(EE / 128, MROWS / 128);  // (16, 32)
    gemm_bf16split<<<gGrid, 256>>>(query,  Wq, bq, qBuf, 1);
    gemm_bf16split<<<gGrid, 256>>>(key_in, Wk, bk, kBuf, 1);
    gemm_bf16split<<<gGrid, 256>>>(value,  Wv, bv, vBuf, 1);

    const int FLASH_SMEM = FLASH_SMEM_BF16 * 2;   // 141312 bytes
    cudaFuncSetAttribute(flash_mma,
                         cudaFuncAttributeMaxDynamicSharedMemorySize, FLASH_SMEM);
    dim3 fGrid(SS / FQ, BB * HH);       // (16, 32)
    flash_mma<<<fGrid, 256, FLASH_SMEM>>>(qBuf, kBuf, vBuf, aoBuf);

    gemm_bf16split<<<gGrid, 256>>>(aoBuf, Wo, bo, out, 0);
}

// round 12
// speedup vs baseline: 2.8537x; 1.0785x over previous
#include <cuda_runtime.h>
#include <cuda_bf16.h>
#include <math.h>

// Problem constants
#define BB 2
#define SS 2048
#define EE 2048
#define HH 16
#define DD 128
#define MROWS (BB * SS)   // 4096

// ---------------- scratch (static device globals; no runtime alloc) ----------
// QKV in pre-split bf16 hi/lo, (B,H,S,D) layout
__device__ __align__(256) __nv_bfloat16 g_Qh[(size_t)BB * HH * SS * DD];
__device__ __align__(256) __nv_bfloat16 g_Ql[(size_t)BB * HH * SS * DD];
__device__ __align__(256) __nv_bfloat16 g_Kh[(size_t)BB * HH * SS * DD];
__device__ __align__(256) __nv_bfloat16 g_Kl[(size_t)BB * HH * SS * DD];
__device__ __align__(256) __nv_bfloat16 g_Vh[(size_t)BB * HH * SS * DD];
__device__ __align__(256) __nv_bfloat16 g_Vl[(size_t)BB * HH * SS * DD];
__device__ __align__(256) float g_AO[(size_t)BB * SS * EE];   // (B,S,E)

// ---------------- mma / ldmatrix / cp.async helpers --------------------------
__device__ __forceinline__ unsigned smem_u32(const void* p) {
    return (unsigned)__cvta_generic_to_shared(p);
}
__device__ __forceinline__ void ldsm4(unsigned* r, unsigned addr) {
    asm volatile("ldmatrix.sync.aligned.m8n8.x4.shared.b16 {%0,%1,%2,%3}, [%4];\n"
                 : "=r"(r[0]), "=r"(r[1]), "=r"(r[2]), "=r"(r[3]) : "r"(addr));
}
__device__ __forceinline__ void ldsm4t(unsigned* r, unsigned addr) {
    asm volatile("ldmatrix.sync.aligned.m8n8.x4.trans.shared.b16 {%0,%1,%2,%3}, [%4];\n"
                 : "=r"(r[0]), "=r"(r[1]), "=r"(r[2]), "=r"(r[3]) : "r"(addr));
}
__device__ __forceinline__ void mma16816(float* c, const unsigned* a,
                                         unsigned b0, unsigned b1) {
    asm volatile(
        "mma.sync.aligned.m16n8k16.row.col.f32.bf16.bf16.f32 "
        "{%0,%1,%2,%3}, {%4,%5,%6,%7}, {%8,%9}, {%0,%1,%2,%3};\n"
        : "+f"(c[0]), "+f"(c[1]), "+f"(c[2]), "+f"(c[3])
        : "r"(a[0]), "r"(a[1]), "r"(a[2]), "r"(a[3]), "r"(b0), "r"(b1));
}
__device__ __forceinline__ float ex2f(float x) {
    float y;
    asm("ex2.approx.ftz.f32 %0, %1;" : "=f"(y) : "f"(x));
    return y;
}
__device__ __forceinline__ void split2(float x, float y, unsigned& hi, unsigned& lo) {
    __nv_bfloat162 h = __floats2bfloat162_rn(x, y);
    __nv_bfloat162 l = __floats2bfloat162_rn(x - __low2float(h), y - __high2float(h));
    hi = *reinterpret_cast<unsigned*>(&h);
    lo = *reinterpret_cast<unsigned*>(&l);
}
__device__ __forceinline__ void cpa16(unsigned smem, const void* g) {
    asm volatile("cp.async.cg.shared.global [%0], [%1], 16;\n"
                 :: "r"(smem), "l"(g));
}
#define CP_COMMIT asm volatile("cp.async.commit_group;\n" ::: "memory")
#define CP_WAIT0  asm volatile("cp.async.wait_group 0;\n" ::: "memory")

// =============================================================================
// Split-bf16 tensor-core GEMM: validated R7 core.
// headSplit=1: write split bf16 hi/lo to (B,H,S,D) arrays Ch/Cl.
// headSplit=0: write fp32 row-major MxN to Cf.
// =============================================================================
#define ASTR 40
#define BSTR 136

__global__ __launch_bounds__(256) void gemm_bf16split(const float* __restrict__ A,
                                                      const float* __restrict__ W,
                                                      const float* __restrict__ bias,
                                                      float* __restrict__ Cf,
                                                      __nv_bfloat16* __restrict__ Ch,
                                                      __nv_bfloat16* __restrict__ Cl,
                                                      int headSplit)
{
    const int K = EE, N = EE;
    __shared__ __align__(16) __nv_bfloat16 Ah[128][ASTR];
    __shared__ __align__(16) __nv_bfloat16 Al[128][ASTR];
    __shared__ __align__(16) __nv_bfloat16 Bh[32][BSTR];
    __shared__ __align__(16) __nv_bfloat16 Bl[32][BSTR];

    const int tid  = threadIdx.x;
    const int lane = tid & 31;
    const int warp = tid >> 5;
    const int wm = (warp & 3) * 32;
    const int wn = (warp >> 2) * 64;
    const int m0 = blockIdx.y * 128;
    const int n0 = blockIdx.x * 128;
    const int lr  = lane & 15;
    const int lk8 = (lane >> 4) * 8;

    float acc[2][8][4];
#pragma unroll
    for (int mt = 0; mt < 2; mt++)
#pragma unroll
        for (int nt = 0; nt < 8; nt++)
#pragma unroll
            for (int j = 0; j < 4; j++) acc[mt][nt][j] = 0.0f;

    float4 pa[4], pb[4];

#define LOAD_TILES(k0)                                                          \
    {                                                                           \
        _Pragma("unroll")                                                       \
        for (int l = 0; l < 4; l++) {                                           \
            int idx = l * 256 + tid;                                            \
            int r = idx >> 3, c = idx & 7;                                      \
            pa[l] = *reinterpret_cast<const float4*>(                           \
                A + (size_t)(m0 + r) * K + (k0) + c * 4);                       \
        }                                                                       \
        _Pragma("unroll")                                                       \
        for (int l = 0; l < 4; l++) {                                           \
            int idx = l * 256 + tid;                                            \
            int r = idx >> 5, c = idx & 31;                                     \
            pb[l] = *reinterpret_cast<const float4*>(                           \
                W + (size_t)((k0) + r) * N + n0 + c * 4);                       \
        }                                                                       \
    }

#define STORE_TILES()                                                           \
    {                                                                           \
        _Pragma("unroll")                                                       \
        for (int l = 0; l < 4; l++) {                                           \
            int idx = l * 256 + tid;                                            \
            int r = idx >> 3, c = (idx & 7) * 4;                                \
            float4 v = pa[l];                                                   \
            unsigned h01, l01, h23, l23;                                        \
            split2(v.x, v.y, h01, l01);                                         \
            split2(v.z, v.w, h23, l23);                                         \
            *reinterpret_cast<unsigned*>(&Ah[r][c])     = h01;                  \
            *reinterpret_cast<unsigned*>(&Ah[r][c + 2]) = h23;                  \
            *reinterpret_cast<unsigned*>(&Al[r][c])     = l01;                  \
            *reinterpret_cast<unsigned*>(&Al[r][c + 2]) = l23;                  \
        }                                                                       \
        _Pragma("unroll")                                                       \
        for (int l = 0; l < 4; l++) {                                           \
            int idx = l * 256 + tid;                                            \
            int r = idx >> 5, c = (idx & 31) * 4;                               \
            float4 v = pb[l];                                                   \
            unsigned h01, l01, h23, l23;                                        \
            split2(v.x, v.y, h01, l01);                                         \
            split2(v.z, v.w, h23, l23);                                         \
            *reinterpret_cast<unsigned*>(&Bh[r][c])     = h01;                  \
            *reinterpret_cast<unsigned*>(&Bh[r][c + 2]) = h23;                  \
            *reinterpret_cast<unsigned*>(&Bl[r][c])     = l01;                  \
            *reinterpret_cast<unsigned*>(&Bl[r][c + 2]) = l23;                  \
        }                                                                       \
    }

    LOAD_TILES(0);
    STORE_TILES();
    __syncthreads();

    for (int k0 = 0; k0 < K; k0 += 32) {
        const bool more = (k0 + 32) < K;
        if (more) LOAD_TILES(k0 + 32);

#pragma unroll
        for (int kk = 0; kk < 32; kk += 16) {
            unsigned ah[2][4], al[2][4];
            ldsm4(ah[0], smem_u32(&Ah[wm + lr][kk + lk8]));
            ldsm4(ah[1], smem_u32(&Ah[wm + 16 + lr][kk + lk8]));
            ldsm4(al[0], smem_u32(&Al[wm + lr][kk + lk8]));
            ldsm4(al[1], smem_u32(&Al[wm + 16 + lr][kk + lk8]));

#pragma unroll
            for (int nb = 0; nb < 4; nb++) {
                unsigned bh[4], bl[4];
                ldsm4t(bh, smem_u32(&Bh[kk + lr][wn + nb * 16 + lk8]));
                ldsm4t(bl, smem_u32(&Bl[kk + lr][wn + nb * 16 + lk8]));
#pragma unroll
                for (int mt = 0; mt < 2; mt++) {
                    mma16816(acc[mt][2 * nb],     ah[mt], bh[0], bh[1]);
                    mma16816(acc[mt][2 * nb + 1], ah[mt], bh[2], bh[3]);
                    mma16816(acc[mt][2 * nb],     ah[mt], bl[0], bl[1]);
                    mma16816(acc[mt][2 * nb + 1], ah[mt], bl[2], bl[3]);
                    mma16816(acc[mt][2 * nb],     al[mt], bh[0], bh[1]);
                    mma16816(acc[mt][2 * nb + 1], al[mt], bh[2], bh[3]);
                }
            }
        }

        if (more) {
            __syncthreads();
            STORE_TILES();
            __syncthreads();
        }
    }

#pragma unroll
    for (int mt = 0; mt < 2; mt++) {
#pragma unroll
        for (int nt = 0; nt < 8; nt++) {
            int n = n0 + wn + nt * 8 + 2 * (lane & 3);
            float b0 = bias[n], b1 = bias[n + 1];
#pragma unroll
            for (int half = 0; half < 2; half++) {
                int m = m0 + wm + mt * 16 + (lane >> 2) + half * 8;
                float vx = acc[mt][nt][2 * half]     + b0;
                float vy = acc[mt][nt][2 * half + 1] + b1;
                if (headSplit) {
                    int bb = m >> 11, ss = m & 2047;
                    int h = n >> 7, d = n & 127;
                    size_t off = (((size_t)bb * HH + h) * SS + ss) * DD + d;
                    unsigned hi, lo;
                    split2(vx, vy, hi, lo);
                    *reinterpret_cast<unsigned*>(&Ch[off]) = hi;
                    *reinterpret_cast<unsigned*>(&Cl[off]) = lo;
                } else {
                    float2 v; v.x = vx; v.y = vy;
                    *reinterpret_cast<float2*>(&Cf[(size_t)m * N + n]) = v;
                }
            }
        }
    }
#undef LOAD_TILES
#undef STORE_TILES
}

// =============================================================================
// Tensor-core flash attention, pipelined cp.async, pre-split bf16 inputs.
// BQ=64 per CTA, 4 warps (warp owns 16 q rows -> warp-local softmax).
// FK=64. Single K and V buffers; V(i) load overlaps S-compute, K(i+1) load
// overlaps PV-compute. 102KB smem -> 2 CTAs/SM.
//   S = Q K^T : A=Q [q][d] ldsm4; B=K natural [kv][d] ldsm4 NON-trans
//   O += P V  : A=P from accum regs; B=V [kv][d] ldsm4t
// =============================================================================
#define FQ  64
#define FK  64
#define FSTR 136                 // smem row stride (bf16), 272B: ldsm-conflict-free
#define FTSZ (64 * FSTR)         // elems per tile array

__global__ __launch_bounds__(128) void flash_mma(
    const __nv_bfloat16* __restrict__ Qhg, const __nv_bfloat16* __restrict__ Qlg,
    const __nv_bfloat16* __restrict__ Khg, const __nv_bfloat16* __restrict__ Klg,
    const __nv_bfloat16* __restrict__ Vhg, const __nv_bfloat16* __restrict__ Vlg,
    float* __restrict__ Og)
{
    extern __shared__ __align__(16) __nv_bfloat16 smb[];
    __nv_bfloat16 (*Qh)[FSTR] = reinterpret_cast<__nv_bfloat16 (*)[FSTR]>(smb);
    __nv_bfloat16 (*Ql)[FSTR] = reinterpret_cast<__nv_bfloat16 (*)[FSTR]>(smb + FTSZ);
    __nv_bfloat16 (*Kh)[FSTR] = reinterpret_cast<__nv_bfloat16 (*)[FSTR]>(smb + 2 * FTSZ);
    __nv_bfloat16 (*Kl)[FSTR] = reinterpret_cast<__nv_bfloat16 (*)[FSTR]>(smb + 3 * FTSZ);
    __nv_bfloat16 (*Vh)[FSTR] = reinterpret_cast<__nv_bfloat16 (*)[FSTR]>(smb + 4 * FTSZ);
    __nv_bfloat16 (*Vl)[FSTR] = reinterpret_cast<__nv_bfloat16 (*)[FSTR]>(smb + 5 * FTSZ);

    const int tid  = threadIdx.x;
    const int lane = tid & 31;
    const int warp = tid >> 5;           // 0..3
    const int wq   = warp * 16;
    const int lr   = lane & 15;
    const int lk8  = (lane >> 4) * 8;
    // K b-frag (non-trans) lane addressing for [n][k] layout
    const int krow = (lane & 7) + ((lane >> 4) << 3);
    const int kcol = ((lane >> 3) & 1) << 3;
    const int bh   = blockIdx.y;
    const int q0   = blockIdx.x * FQ;
    const size_t base = (size_t)bh * SS * DD;

    const float kscale = 0.088388347648318447f * 1.4426950408889634f;

    // 64x128 bf16 tile loader: 1024 16B-chunks per array, 8 per thread
#define CP_TILE(SH, SL, GH, GL, goff)                                           \
    {                                                                           \
        _Pragma("unroll")                                                       \
        for (int l = 0; l < 8; l++) {                                           \
            int idx = l * 128 + tid;                                            \
            int r = idx >> 4, c = (idx & 15) * 8;                               \
            cpa16(smem_u32(&SH[r][c]), GH + (goff) + (size_t)r * DD + c);       \
            cpa16(smem_u32(&SL[r][c]), GL + (goff) + (size_t)r * DD + c);       \
        }                                                                       \
    }

    // prologue: Q + K(0)
    CP_TILE(Qh, Ql, Qhg, Qlg, base + (size_t)q0 * DD);
    CP_TILE(Kh, Kl, Khg, Klg, base);
    CP_COMMIT;

    float oa[16][4];
#pragma unroll
    for (int nt = 0; nt < 16; nt++)
#pragma unroll
        for (int j = 0; j < 4; j++) oa[nt][j] = 0.0f;
    float m0 = -1e30f, m1 = -1e30f;
    float l0 = 0.0f,  l1 = 0.0f;

    CP_WAIT0;
    __syncthreads();

    for (int kb = 0; kb < SS; kb += FK) {
        // V(kb) load overlaps S compute
        CP_TILE(Vh, Vl, Vhg, Vlg, base + (size_t)kb * DD);
        CP_COMMIT;

        // ---- S = Q K^T ----
        float sa[8][4];
#pragma unroll
        for (int nt = 0; nt < 8; nt++)
#pragma unroll
            for (int j = 0; j < 4; j++) sa[nt][j] = 0.0f;

#pragma unroll
        for (int kk = 0; kk < 8; kk++) {
            unsigned qh[4], qlo[4];
            ldsm4(qh,  smem_u32(&Qh[wq + lr][kk * 16 + lk8]));
            ldsm4(qlo, smem_u32(&Ql[wq + lr][kk * 16 + lk8]));
#pragma unroll
            for (int nb = 0; nb < 4; nb++) {
                unsigned kh[4], kl[4];
                ldsm4(kh, smem_u32(&Kh[nb * 16 + krow][kk * 16 + kcol]));
                ldsm4(kl, smem_u32(&Kl[nb * 16 + krow][kk * 16 + kcol]));
                mma16816(sa[2 * nb],     qh,  kh[0], kh[1]);
                mma16816(sa[2 * nb + 1], qh,  kh[2], kh[3]);
                mma16816(sa[2 * nb],     qh,  kl[0], kl[1]);
                mma16816(sa[2 * nb + 1], qh,  kl[2], kl[3]);
                mma16816(sa[2 * nb],     qlo, kh[0], kh[1]);
                mma16816(sa[2 * nb + 1], qlo, kh[2], kh[3]);
            }
        }

        // ---- online softmax (warp-local) ----
        float mx0 = -1e30f, mx1 = -1e30f;
#pragma unroll
        for (int nt = 0; nt < 8; nt++) {
            sa[nt][0] *= kscale; sa[nt][1] *= kscale;
            sa[nt][2] *= kscale; sa[nt][3] *= kscale;
            mx0 = fmaxf(mx0, fmaxf(sa[nt][0], sa[nt][1]));
            mx1 = fmaxf(mx1, fmaxf(sa[nt][2], sa[nt][3]));
        }
        mx0 = fmaxf(mx0, __shfl_xor_sync(0xffffffffu, mx0, 1));
        mx0 = fmaxf(mx0, __shfl_xor_sync(0xffffffffu, mx0, 2));
        mx1 = fmaxf(mx1, __shfl_xor_sync(0xffffffffu, mx1, 1));
        mx1 = fmaxf(mx1, __shfl_xor_sync(0xffffffffu, mx1, 2));

        float mn0 = fmaxf(m0, mx0);
        float mn1 = fmaxf(m1, mx1);
        float c0 = ex2f(m0 - mn0);
        float c1 = ex2f(m1 - mn1);

        float rs0 = 0.0f, rs1 = 0.0f;
#pragma unroll
        for (int nt = 0; nt < 8; nt++) {
            sa[nt][0] = ex2f(sa[nt][0] - mn0);
            sa[nt][1] = ex2f(sa[nt][1] - mn0);
            sa[nt][2] = ex2f(sa[nt][2] - mn1);
            sa[nt][3] = ex2f(sa[nt][3] - mn1);
            rs0 += sa[nt][0] + sa[nt][1];
            rs1 += sa[nt][2] + sa[nt][3];
        }
        rs0 += __shfl_xor_sync(0xffffffffu, rs0, 1);
        rs0 += __shfl_xor_sync(0xffffffffu, rs0, 2);
        rs1 += __shfl_xor_sync(0xffffffffu, rs1, 1);
        rs1 += __shfl_xor_sync(0xffffffffu, rs1, 2);

        l0 = l0 * c0 + rs0;  m0 = mn0;
        l1 = l1 * c1 + rs1;  m1 = mn1;
#pragma unroll
        for (int nt = 0; nt < 16; nt++) {
            oa[nt][0] *= c0; oa[nt][1] *= c0;
            oa[nt][2] *= c1; oa[nt][3] *= c1;
        }

        // V ready; all warps done reading K smem -> start K(kb+FK) load
        CP_WAIT0;
        __syncthreads();
        if (kb + FK < SS) {
            CP_TILE(Kh, Kl, Khg, Klg, base + (size_t)(kb + FK) * DD);
            CP_COMMIT;
        }

        // ---- O += P V (K(next) load overlaps) ----
#pragma unroll
        for (int kc = 0; kc < 4; kc++) {
            unsigned pha[4], pla[4];
            split2(sa[2 * kc][0],     sa[2 * kc][1],     pha[0], pla[0]);
            split2(sa[2 * kc][2],     sa[2 * kc][3],     pha[1], pla[1]);
            split2(sa[2 * kc + 1][0], sa[2 * kc + 1][1], pha[2], pla[2]);
            split2(sa[2 * kc + 1][2], sa[2 * kc + 1][3], pha[3], pla[3]);
#pragma unroll
            for (int nb = 0; nb < 8; nb++) {
                unsigned vh[4], vl[4];
                ldsm4t(vh, smem_u32(&Vh[kc * 16 + lr][nb * 16 + lk8]));
                ldsm4t(vl, smem_u32(&Vl[kc * 16 + lr][nb * 16 + lk8]));
                mma16816(oa[2 * nb],     pha, vh[0], vh[1]);
                mma16816(oa[2 * nb + 1], pha, vh[2], vh[3]);
                mma16816(oa[2 * nb],     pha, vl[0], vl[1]);
                mma16816(oa[2 * nb + 1], pha, vl[2], vl[3]);
                mma16816(oa[2 * nb],     pla, vh[0], vh[1]);
                mma16816(oa[2 * nb + 1], pla, vh[2], vh[3]);
            }
        }

        // K(next) ready; all warps done reading V smem
        CP_WAIT0;
        __syncthreads();
    }

    // ---- normalize, write to (B,S,E) ----
    const int b = bh >> 4;
    const int h = bh & 15;
    const float inv0 = 1.0f / l0;
    const float inv1 = 1.0f / l1;
    const int r0 = q0 + wq + (lane >> 2);
    const int d0 = (lane & 3) * 2;
#pragma unroll
    for (int nt = 0; nt < 16; nt++) {
        int d = nt * 8 + d0;
        float2 v0, v1;
        v0.x = oa[nt][0] * inv0; v0.y = oa[nt][1] * inv0;
        v1.x = oa[nt][2] * inv1; v1.y = oa[nt][3] * inv1;
        *reinterpret_cast<float2*>(
            &Og[((size_t)b * SS + r0) * EE + h * DD + d]) = v0;
        *reinterpret_cast<float2*>(
            &Og[((size_t)b * SS + r0 + 8) * EE + h * DD + d]) = v1;
    }
#undef CP_TILE
}

// =============================================================================
// Launch
// =============================================================================
extern "C" void kernel_launch(void* const* d_in, const int* in_sizes, int n_in,
                              void* d_out, int out_size)
{
    const float* query  = (const float*)d_in[0];
    const float* key_in = (const float*)d_in[1];
    const float* value  = (const float*)d_in[2];
    const float* Wq = (const float*)d_in[3];
    const float* bq = (const float*)d_in[4];
    const float* Wk = (const float*)d_in[5];
    const float* bk = (const float*)d_in[6];
    const float* Wv = (const float*)d_in[7];
    const float* bv = (const float*)d_in[8];
    const float* Wo = (const float*)d_in[9];
    const float* bo = (const float*)d_in[10];
    float* out = (float*)d_out;

    __nv_bfloat16 *qh, *ql, *kh, *kl, *vh, *vl;
    float* aoBuf;
    cudaGetSymbolAddress((void**)&qh, g_Qh);
    cudaGetSymbolAddress((void**)&ql, g_Ql);
    cudaGetSymbolAddress((void**)&kh, g_Kh);
    cudaGetSymbolAddress((void**)&kl, g_Kl);
    cudaGetSymbolAddress((void**)&vh, g_Vh);
    cudaGetSymbolAddress((void**)&vl, g_Vl);
    cudaGetSymbolAddress((void**)&aoBuf, g_AO);

    dim3 gGrid(EE / 128, MROWS / 128);  // (16, 32)
    gemm_bf16split<<<gGrid, 256>>>(query,  Wq, bq, nullptr, qh, ql, 1);
    gemm_bf16split<<<gGrid, 256>>>(key_in, Wk, bk, nullptr, kh, kl, 1);
    gemm_bf16split<<<gGrid, 256>>>(value,  Wv, bv, nullptr, vh, vl, 1);

    const int FLASH_SMEM = 6 * FTSZ * 2;   // 104448 bytes -> 2 CTAs/SM
    cudaFuncSetAttribute(flash_mma,
                         cudaFuncAttributeMaxDynamicSharedMemorySize, FLASH_SMEM);
    dim3 fGrid(SS / FQ, BB * HH);          // (32, 32)
    flash_mma<<<fGrid, 128, FLASH_SMEM>>>(qh, ql, kh, kl, vh, vl, aoBuf);

    gemm_bf16split<<<gGrid, 256>>>(aoBuf, Wo, bo, out, nullptr, nullptr, 0);
}

// round 17
// speedup vs baseline: 2.9061x; 1.0183x over previous
#include <cuda_runtime.h>
#include <cuda_bf16.h>
#include <math.h>

// Problem constants
#define BB 2
#define SS 2048
#define EE 2048
#define HH 16
#define DD 128
#define MROWS (BB * SS)   // 4096

// ---------------- scratch (static device globals; no runtime alloc) ----------
// pre-split inputs (3 x MROWS x EE) and weights (4 x EE x EE)
__device__ __align__(256) __nv_bfloat16 g_INh[(size_t)3 * MROWS * EE];
__device__ __align__(256) __nv_bfloat16 g_INl[(size_t)3 * MROWS * EE];
__device__ __align__(256) __nv_bfloat16 g_Wh[(size_t)4 * EE * EE];
__device__ __align__(256) __nv_bfloat16 g_Wl[(size_t)4 * EE * EE];
// QKV in split bf16 hi/lo, (B,H,S,D) layout
__device__ __align__(256) __nv_bfloat16 g_Qh[(size_t)BB * HH * SS * DD];
__device__ __align__(256) __nv_bfloat16 g_Ql[(size_t)BB * HH * SS * DD];
__device__ __align__(256) __nv_bfloat16 g_Kh[(size_t)BB * HH * SS * DD];
__device__ __align__(256) __nv_bfloat16 g_Kl[(size_t)BB * HH * SS * DD];
__device__ __align__(256) __nv_bfloat16 g_Vh[(size_t)BB * HH * SS * DD];
__device__ __align__(256) __nv_bfloat16 g_Vl[(size_t)BB * HH * SS * DD];
// attention output, split bf16, (B,S,E) row-major
__device__ __align__(256) __nv_bfloat16 g_AOh[(size_t)MROWS * EE];
__device__ __align__(256) __nv_bfloat16 g_AOl[(size_t)MROWS * EE];

// ---------------- mma / ldmatrix / cp.async helpers --------------------------
__device__ __forceinline__ unsigned smem_u32(const void* p) {
    return (unsigned)__cvta_generic_to_shared(p);
}
__device__ __forceinline__ void ldsm4(unsigned* r, unsigned addr) {
    asm volatile("ldmatrix.sync.aligned.m8n8.x4.shared.b16 {%0,%1,%2,%3}, [%4];\n"
                 : "=r"(r[0]), "=r"(r[1]), "=r"(r[2]), "=r"(r[3]) : "r"(addr));
}
__device__ __forceinline__ void ldsm4t(unsigned* r, unsigned addr) {
    asm volatile("ldmatrix.sync.aligned.m8n8.x4.trans.shared.b16 {%0,%1,%2,%3}, [%4];\n"
                 : "=r"(r[0]), "=r"(r[1]), "=r"(r[2]), "=r"(r[3]) : "r"(addr));
}
__device__ __forceinline__ void mma16816(float* c, const unsigned* a,
                                         unsigned b0, unsigned b1) {
    asm volatile(
        "mma.sync.aligned.m16n8k16.row.col.f32.bf16.bf16.f32 "
        "{%0,%1,%2,%3}, {%4,%5,%6,%7}, {%8,%9}, {%0,%1,%2,%3};\n"
        : "+f"(c[0]), "+f"(c[1]), "+f"(c[2]), "+f"(c[3])
        : "r"(a[0]), "r"(a[1]), "r"(a[2]), "r"(a[3]), "r"(b0), "r"(b1));
}
__device__ __forceinline__ float ex2f(float x) {
    float y;
    asm("ex2.approx.ftz.f32 %0, %1;" : "=f"(y) : "f"(x));
    return y;
}
__device__ __forceinline__ void split2(float x, float y, unsigned& hi, unsigned& lo) {
    __nv_bfloat162 h = __floats2bfloat162_rn(x, y);
    __nv_bfloat162 l = __floats2bfloat162_rn(x - __low2float(h), y - __high2float(h));
    hi = *reinterpret_cast<unsigned*>(&h);
    lo = *reinterpret_cast<unsigned*>(&l);
}
__device__ __forceinline__ void cpa16(unsigned smem, const void* g) {
    asm volatile("cp.async.cg.shared.global [%0], [%1], 16;\n"
                 :: "r"(smem), "l"(g));
}
#define CP_COMMIT asm volatile("cp.async.commit_group;\n" ::: "memory")
#define CP_WAIT0  asm volatile("cp.async.wait_group 0;\n" ::: "memory")
#define CP_WAIT1  asm volatile("cp.async.wait_group 1;\n" ::: "memory")

// =============================================================================
// Pre-pass: split fp32 tensor into bf16 hi + lo residual. Memory-bound.
// =============================================================================
__global__ __launch_bounds__(256) void split_f32(const float* __restrict__ x,
                                                 __nv_bfloat16* __restrict__ h,
                                                 __nv_bfloat16* __restrict__ l,
                                                 int n4)
{
    int i = blockIdx.x * blockDim.x + threadIdx.x;
    if (i < n4) {
        float4 v = reinterpret_cast<const float4*>(x)[i];
        unsigned h01, l01, h23, l23;
        split2(v.x, v.y, h01, l01);
        split2(v.z, v.w, h23, l23);
        uint2 hh, ll;
        hh.x = h01; hh.y = h23;
        ll.x = l01; ll.y = l23;
        reinterpret_cast<uint2*>(h)[i] = hh;
        reinterpret_cast<uint2*>(l)[i] = ll;
    }
}

// =============================================================================
// Pre-split bf16 GEMM: C = (Ah+Al)(Bh+Bl) + bias ~= AhBh + AhBl + AlBh.
// All operands already split -> main loop is pure cp.async -> ldsm -> mma.
// Block tile 128x128, BK=32, 2-stage cp.async double buffer, 256 threads,
// 8 warps (4x2), warp tile 32x64. 75.8KB smem -> 2 CTAs/SM.
// headSplit=1: write split bf16 hi/lo (B,H,S,D); else fp32 row-major.
// =============================================================================
#define GA_H 0
#define GA_L 5120            // 128*40
#define GB_H 10240
#define GB_L 14592           // +32*136
#define G_STAGE 18944        // elems per stage

__global__ __launch_bounds__(256) void gemm_pre(
    const __nv_bfloat16* __restrict__ Ahg, const __nv_bfloat16* __restrict__ Alg,
    const __nv_bfloat16* __restrict__ Bhg, const __nv_bfloat16* __restrict__ Blg,
    const float* __restrict__ bias,
    float* __restrict__ Cf,
    __nv_bfloat16* __restrict__ Ch, __nv_bfloat16* __restrict__ Cl,
    int headSplit)
{
    extern __shared__ __align__(16) __nv_bfloat16 gsm[];
    const int K = EE, N = EE;
    const int tid  = threadIdx.x;
    const int lane = tid & 31;
    const int warp = tid >> 5;
    const int wm = (warp & 3) * 32;
    const int wn = (warp >> 2) * 64;
    const int m0 = blockIdx.y * 128;
    const int n0 = blockIdx.x * 128;
    const int lr  = lane & 15;
    const int lk8 = (lane >> 4) * 8;

    float acc[2][8][4];
#pragma unroll
    for (int mt = 0; mt < 2; mt++)
#pragma unroll
        for (int nt = 0; nt < 8; nt++)
#pragma unroll
            for (int j = 0; j < 4; j++) acc[mt][nt][j] = 0.0f;

#define GLOAD(st, k0)                                                           \
    {                                                                           \
        __nv_bfloat16* sb = gsm + (st) * G_STAGE;                               \
        _Pragma("unroll")                                                       \
        for (int l = 0; l < 2; l++) {                                           \
            int idx = l * 256 + tid;                                            \
            int r = idx >> 2, c = (idx & 3) * 8;                                \
            cpa16(smem_u32(sb + GA_H + r * 40 + c),                             \
                  Ahg + (size_t)(m0 + r) * K + (k0) + c);                       \
            cpa16(smem_u32(sb + GA_L + r * 40 + c),                             \
                  Alg + (size_t)(m0 + r) * K + (k0) + c);                       \
        }                                                                       \
        _Pragma("unroll")                                                       \
        for (int l = 0; l < 2; l++) {                                           \
            int idx = l * 256 + tid;                                            \
            int r = idx >> 4, c = (idx & 15) * 8;                               \
            cpa16(smem_u32(sb + GB_H + r * 136 + c),                            \
                  Bhg + (size_t)((k0) + r) * N + n0 + c);                       \
            cpa16(smem_u32(sb + GB_L + r * 136 + c),                            \
                  Blg + (size_t)((k0) + r) * N + n0 + c);                       \
        }                                                                       \
    }

    GLOAD(0, 0);  CP_COMMIT;
    GLOAD(1, 32); CP_COMMIT;

    const int iters = K / 32;   // 64
    for (int it = 0; it < iters; it++) {
        CP_WAIT1;               // oldest stage resident
        __syncthreads();

        __nv_bfloat16* sb = gsm + (it & 1) * G_STAGE;
        __nv_bfloat16 (*Ah)[40]  = reinterpret_cast<__nv_bfloat16 (*)[40]>(sb + GA_H);
        __nv_bfloat16 (*Al)[40]  = reinterpret_cast<__nv_bfloat16 (*)[40]>(sb + GA_L);
        __nv_bfloat16 (*Bh)[136] = reinterpret_cast<__nv_bfloat16 (*)[136]>(sb + GB_H);
        __nv_bfloat16 (*Bl)[136] = reinterpret_cast<__nv_bfloat16 (*)[136]>(sb + GB_L);

#pragma unroll
        for (int kk = 0; kk < 32; kk += 16) {
            unsigned ah[2][4], al[2][4];
            ldsm4(ah[0], smem_u32(&Ah[wm + lr][kk + lk8]));
            ldsm4(ah[1], smem_u32(&Ah[wm + 16 + lr][kk + lk8]));
            ldsm4(al[0], smem_u32(&Al[wm + lr][kk + lk8]));
            ldsm4(al[1], smem_u32(&Al[wm + 16 + lr][kk + lk8]));

#pragma unroll
            for (int nb = 0; nb < 4; nb++) {
                unsigned bh[4], bl[4];
                ldsm4t(bh, smem_u32(&Bh[kk + lr][wn + nb * 16 + lk8]));
                ldsm4t(bl, smem_u32(&Bl[kk + lr][wn + nb * 16 + lk8]));
#pragma unroll
                for (int mt = 0; mt < 2; mt++) {
                    mma16816(acc[mt][2 * nb],     ah[mt], bh[0], bh[1]);
                    mma16816(acc[mt][2 * nb + 1], ah[mt], bh[2], bh[3]);
                    mma16816(acc[mt][2 * nb],     ah[mt], bl[0], bl[1]);
                    mma16816(acc[mt][2 * nb + 1], ah[mt], bl[2], bl[3]);
                    mma16816(acc[mt][2 * nb],     al[mt], bh[0], bh[1]);
                    mma16816(acc[mt][2 * nb + 1], al[mt], bh[2], bh[3]);
                }
            }
        }

        __syncthreads();        // all warps done with this stage
        if (it + 2 < iters) GLOAD(it & 1, (it + 2) * 32);
        CP_COMMIT;              // commit (possibly empty) keeps group count
    }

    // ---- epilogue ----
#pragma unroll
    for (int mt = 0; mt < 2; mt++) {
#pragma unroll
        for (int nt = 0; nt < 8; nt++) {
            int n = n0 + wn + nt * 8 + 2 * (lane & 3);
            float b0 = bias[n], b1 = bias[n + 1];
#pragma unroll
            for (int half = 0; half < 2; half++) {
                int m = m0 + wm + mt * 16 + (lane >> 2) + half * 8;
                float vx = acc[mt][nt][2 * half]     + b0;
                float vy = acc[mt][nt][2 * half + 1] + b1;
                if (headSplit) {
                    int bb = m >> 11, ss = m & 2047;
                    int h = n >> 7, d = n & 127;
                    size_t off = (((size_t)bb * HH + h) * SS + ss) * DD + d;
                    unsigned hi, lo;
                    split2(vx, vy, hi, lo);
                    *reinterpret_cast<unsigned*>(&Ch[off]) = hi;
                    *reinterpret_cast<unsigned*>(&Cl[off]) = lo;
                } else {
                    float2 v; v.x = vx; v.y = vy;
                    *reinterpret_cast<float2*>(&Cf[(size_t)m * N + n]) = v;
                }
            }
        }
    }
#undef GLOAD
}

// =============================================================================
// Tensor-core flash attention, pipelined cp.async, pre-split bf16 in/out.
// (validated R12 core; epilogue now emits split bf16 for the O-projection)
// =============================================================================
#define FQ  64
#define FK  64
#define FSTR 136
#define FTSZ (64 * FSTR)

__global__ __launch_bounds__(128) void flash_mma(
    const __nv_bfloat16* __restrict__ Qhg, const __nv_bfloat16* __restrict__ Qlg,
    const __nv_bfloat16* __restrict__ Khg, const __nv_bfloat16* __restrict__ Klg,
    const __nv_bfloat16* __restrict__ Vhg, const __nv_bfloat16* __restrict__ Vlg,
    __nv_bfloat16* __restrict__ AOh, __nv_bfloat16* __restrict__ AOl)
{
    extern __shared__ __align__(16) __nv_bfloat16 smb[];
    __nv_bfloat16 (*Qh)[FSTR] = reinterpret_cast<__nv_bfloat16 (*)[FSTR]>(smb);
    __nv_bfloat16 (*Ql)[FSTR] = reinterpret_cast<__nv_bfloat16 (*)[FSTR]>(smb + FTSZ);
    __nv_bfloat16 (*Kh)[FSTR] = reinterpret_cast<__nv_bfloat16 (*)[FSTR]>(smb + 2 * FTSZ);
    __nv_bfloat16 (*Kl)[FSTR] = reinterpret_cast<__nv_bfloat16 (*)[FSTR]>(smb + 3 * FTSZ);
    __nv_bfloat16 (*Vh)[FSTR] = reinterpret_cast<__nv_bfloat16 (*)[FSTR]>(smb + 4 * FTSZ);
    __nv_bfloat16 (*Vl)[FSTR] = reinterpret_cast<__nv_bfloat16 (*)[FSTR]>(smb + 5 * FTSZ);

    const int tid  = threadIdx.x;
    const int lane = tid & 31;
    const int warp = tid >> 5;
    const int wq   = warp * 16;
    const int lr   = lane & 15;
    const int lk8  = (lane >> 4) * 8;
    const int krow = (lane & 7) + ((lane >> 4) << 3);
    const int kcol = ((lane >> 3) & 1) << 3;
    const int bh   = blockIdx.y;
    const int q0   = blockIdx.x * FQ;
    const size_t base = (size_t)bh * SS * DD;

    const float kscale = 0.088388347648318447f * 1.4426950408889634f;

#define CP_TILE(SH, SL, GH, GL, goff)                                           \
    {                                                                           \
        _Pragma("unroll")                                                       \
        for (int l = 0; l < 8; l++) {                                           \
            int idx = l * 128 + tid;                                            \
            int r = idx >> 4, c = (idx & 15) * 8;                               \
            cpa16(smem_u32(&SH[r][c]), GH + (goff) + (size_t)r * DD + c);       \
            cpa16(smem_u32(&SL[r][c]), GL + (goff) + (size_t)r * DD + c);       \
        }                                                                       \
    }

    CP_TILE(Qh, Ql, Qhg, Qlg, base + (size_t)q0 * DD);
    CP_TILE(Kh, Kl, Khg, Klg, base);
    CP_COMMIT;

    float oa[16][4];
#pragma unroll
    for (int nt = 0; nt < 16; nt++)
#pragma unroll
        for (int j = 0; j < 4; j++) oa[nt][j] = 0.0f;
    float m0 = -1e30f, m1 = -1e30f;
    float l0 = 0.0f,  l1 = 0.0f;

    CP_WAIT0;
    __syncthreads();

    for (int kb = 0; kb < SS; kb += FK) {
        CP_TILE(Vh, Vl, Vhg, Vlg, base + (size_t)kb * DD);
        CP_COMMIT;

        float sa[8][4];
#pragma unroll
        for (int nt = 0; nt < 8; nt++)
#pragma unroll
            for (int j = 0; j < 4; j++) sa[nt][j] = 0.0f;

#pragma unroll
        for (int kk = 0; kk < 8; kk++) {
            unsigned qh[4], qlo[4];
            ldsm4(qh,  smem_u32(&Qh[wq + lr][kk * 16 + lk8]));
            ldsm4(qlo, smem_u32(&Ql[wq + lr][kk * 16 + lk8]));
#pragma unroll
            for (int nb = 0; nb < 4; nb++) {
                unsigned kh[4], kl[4];
                ldsm4(kh, smem_u32(&Kh[nb * 16 + krow][kk * 16 + kcol]));
                ldsm4(kl, smem_u32(&Kl[nb * 16 + krow][kk * 16 + kcol]));
                mma16816(sa[2 * nb],     qh,  kh[0], kh[1]);
                mma16816(sa[2 * nb + 1], qh,  kh[2], kh[3]);
                mma16816(sa[2 * nb],     qh,  kl[0], kl[1]);
                mma16816(sa[2 * nb + 1], qh,  kl[2], kl[3]);
                mma16816(sa[2 * nb],     qlo, kh[0], kh[1]);
                mma16816(sa[2 * nb + 1], qlo, kh[2], kh[3]);
            }
        }

        float mx0 = -1e30f, mx1 = -1e30f;
#pragma unroll
        for (int nt = 0; nt < 8; nt++) {
            sa[nt][0] *= kscale; sa[nt][1] *= kscale;
            sa[nt][2] *= kscale; sa[nt][3] *= kscale;
            mx0 = fmaxf(mx0, fmaxf(sa[nt][0], sa[nt][1]));
            mx1 = fmaxf(mx1, fmaxf(sa[nt][2], sa[nt][3]));
        }
        mx0 = fmaxf(mx0, __shfl_xor_sync(0xffffffffu, mx0, 1));
        mx0 = fmaxf(mx0, __shfl_xor_sync(0xffffffffu, mx0, 2));
        mx1 = fmaxf(mx1, __shfl_xor_sync(0xffffffffu, mx1, 1));
        mx1 = fmaxf(mx1, __shfl_xor_sync(0xffffffffu, mx1, 2));

        float mn0 = fmaxf(m0, mx0);
        float mn1 = fmaxf(m1, mx1);
        float c0 = ex2f(m0 - mn0);
        float c1 = ex2f(m1 - mn1);

        float rs0 = 0.0f, rs1 = 0.0f;
#pragma unroll
        for (int nt = 0; nt < 8; nt++) {
            sa[nt][0] = ex2f(sa[nt][0] - mn0);
            sa[nt][1] = ex2f(sa[nt][1] - mn0);
            sa[nt][2] = ex2f(sa[nt][2] - mn1);
            sa[nt][3] = ex2f(sa[nt][3] - mn1);
            rs0 += sa[nt][0] + sa[nt][1];
            rs1 += sa[nt][2] + sa[nt][3];
        }
        rs0 += __shfl_xor_sync(0xffffffffu, rs0, 1);
        rs0 += __shfl_xor_sync(0xffffffffu, rs0, 2);
        rs1 += __shfl_xor_sync(0xffffffffu, rs1, 1);
        rs1 += __shfl_xor_sync(0xffffffffu, rs1, 2);

        l0 = l0 * c0 + rs0;  m0 = mn0;
        l1 = l1 * c1 + rs1;  m1 = mn1;
#pragma unroll
        for (int nt = 0; nt < 16; nt++) {
            oa[nt][0] *= c0; oa[nt][1] *= c0;
            oa[nt][2] *= c1; oa[nt][3] *= c1;
        }

        CP_WAIT0;
        __syncthreads();
        if (kb + FK < SS) {
            CP_TILE(Kh, Kl, Khg, Klg, base + (size_t)(kb + FK) * DD);
            CP_COMMIT;
        }

#pragma unroll
        for (int kc = 0; kc < 4; kc++) {
            unsigned pha[4], pla[4];
            split2(sa[2 * kc][0],     sa[2 * kc][1],     pha[0], pla[0]);
            split2(sa[2 * kc][2],     sa[2 * kc][3],     pha[1], pla[1]);
            split2(sa[2 * kc + 1][0], sa[2 * kc + 1][1], pha[2], pla[2]);
            split2(sa[2 * kc + 1][2], sa[2 * kc + 1][3], pha[3], pla[3]);
#pragma unroll
            for (int nb = 0; nb < 8; nb++) {
                unsigned vh[4], vl[4];
                ldsm4t(vh, smem_u32(&Vh[kc * 16 + lr][nb * 16 + lk8]));
                ldsm4t(vl, smem_u32(&Vl[kc * 16 + lr][nb * 16 + lk8]));
                mma16816(oa[2 * nb],     pha, vh[0], vh[1]);
                mma16816(oa[2 * nb + 1], pha, vh[2], vh[3]);
                mma16816(oa[2 * nb],     pha, vl[0], vl[1]);
                mma16816(oa[2 * nb + 1], pha, vl[2], vl[3]);
                mma16816(oa[2 * nb],     pla, vh[0], vh[1]);
                mma16816(oa[2 * nb + 1], pla, vh[2], vh[3]);
            }
        }

        CP_WAIT0;
        __syncthreads();
    }

    // ---- normalize, split, write (B,S,E) bf16 hi/lo ----
    const int b = bh >> 4;
    const int h = bh & 15;
    const float inv0 = 1.0f / l0;
    const float inv1 = 1.0f / l1;
    const int r0 = q0 + wq + (lane >> 2);
    const int d0 = (lane & 3) * 2;
#pragma unroll
    for (int nt = 0; nt < 16; nt++) {
        int d = nt * 8 + d0;
        size_t off0 = ((size_t)b * SS + r0) * EE + h * DD + d;
        size_t off1 = ((size_t)b * SS + r0 + 8) * EE + h * DD + d;
        unsigned hi, lo;
        split2(oa[nt][0] * inv0, oa[nt][1] * inv0, hi, lo);
        *reinterpret_cast<unsigned*>(&AOh[off0]) = hi;
        *reinterpret_cast<unsigned*>(&AOl[off0]) = lo;
        split2(oa[nt][2] * inv1, oa[nt][3] * inv1, hi, lo);
        *reinterpret_cast<unsigned*>(&AOh[off1]) = hi;
        *reinterpret_cast<unsigned*>(&AOl[off1]) = lo;
    }
#undef CP_TILE
}

// =============================================================================
// Launch
// =============================================================================
extern "C" void kernel_launch(void* const* d_in, const int* in_sizes, int n_in,
                              void* d_out, int out_size)
{
    const float* query  = (const float*)d_in[0];
    const float* key_in = (const float*)d_in[1];
    const float* value  = (const float*)d_in[2];
    const float* Wq = (const float*)d_in[3];
    const float* bq = (const float*)d_in[4];
    const float* Wk = (const float*)d_in[5];
    const float* bk = (const float*)d_in[6];
    const float* Wv = (const float*)d_in[7];
    const float* bv = (const float*)d_in[8];
    const float* Wo = (const float*)d_in[9];
    const float* bo = (const float*)d_in[10];
    float* out = (float*)d_out;

    __nv_bfloat16 *inh, *inl, *wh, *wl;
    __nv_bfloat16 *qh, *ql, *kh, *kl, *vh, *vl, *aoh, *aol;
    cudaGetSymbolAddress((void**)&inh, g_INh);
    cudaGetSymbolAddress((void**)&inl, g_INl);
    cudaGetSymbolAddress((void**)&wh,  g_Wh);
    cudaGetSymbolAddress((void**)&wl,  g_Wl);
    cudaGetSymbolAddress((void**)&qh,  g_Qh);
    cudaGetSymbolAddress((void**)&ql,  g_Ql);
    cudaGetSymbolAddress((void**)&kh,  g_Kh);
    cudaGetSymbolAddress((void**)&kl,  g_Kl);
    cudaGetSymbolAddress((void**)&vh,  g_Vh);
    cudaGetSymbolAddress((void**)&vl,  g_Vl);
    cudaGetSymbolAddress((void**)&aoh, g_AOh);
    cudaGetSymbolAddress((void**)&aol, g_AOl);

    const size_t INSZ = (size_t)MROWS * EE;   // 8.39M elems
    const size_t WSZ  = (size_t)EE * EE;      // 4.19M elems

    // ---- pre-pass: split activations + weights ----
    {
        int n4i = (int)(INSZ / 4), n4w = (int)(WSZ / 4);
        int gi = (n4i + 255) / 256, gw = (n4w + 255) / 256;
        split_f32<<<gi, 256>>>(query,  inh,            inl,            n4i);
        split_f32<<<gi, 256>>>(key_in, inh + INSZ,     inl + INSZ,     n4i);
        split_f32<<<gi, 256>>>(value,  inh + 2 * INSZ, inl + 2 * INSZ, n4i);
        split_f32<<<gw, 256>>>(Wq, wh,           wl,           n4w);
        split_f32<<<gw, 256>>>(Wk, wh + WSZ,     wl + WSZ,     n4w);
        split_f32<<<gw, 256>>>(Wv, wh + 2 * WSZ, wl + 2 * WSZ, n4w);
        split_f32<<<gw, 256>>>(Wo, wh + 3 * WSZ, wl + 3 * WSZ, n4w);
    }

    const int GEMM_SMEM = 2 * G_STAGE * 2;   // 75776 bytes -> 2 CTAs/SM
    cudaFuncSetAttribute(gemm_pre,
                         cudaFuncAttributeMaxDynamicSharedMemorySize, GEMM_SMEM);

    dim3 gGrid(EE / 128, MROWS / 128);  // (16, 32)
    gemm_pre<<<gGrid, 256, GEMM_SMEM>>>(inh,            inl,            wh,           wl,
                                        bq, nullptr, qh, ql, 1);
    gemm_pre<<<gGrid, 256, GEMM_SMEM>>>(inh + INSZ,     inl + INSZ,     wh + WSZ,     wl + WSZ,
                                        bk, nullptr, kh, kl, 1);
    gemm_pre<<<gGrid, 256, GEMM_SMEM>>>(inh + 2 * INSZ, inl + 2 * INSZ, wh + 2 * WSZ, wl + 2 * WSZ,
                                        bv, nullptr, vh, vl, 1);

    const int FLASH_SMEM = 6 * FTSZ * 2;   // 104448 bytes -> 2 CTAs/SM
    cudaFuncSetAttribute(flash_mma,
                         cudaFuncAttributeMaxDynamicSharedMemorySize, FLASH_SMEM);
    dim3 fGrid(SS / FQ, BB * HH);          // (32, 32)
    flash_mma<<<fGrid, 128, FLASH_SMEM>>>(qh, ql, kh, kl, vh, vl, aoh, aol);

    gemm_pre<<<gGrid, 256, GEMM_SMEM>>>(aoh, aol, wh + 3 * WSZ, wl + 3 * WSZ,
                                        bo, out, nullptr, nullptr, 0);
}